// round 1
// baseline (speedup 1.0000x reference)
#include <cuda_runtime.h>
#include <cuda_bf16.h>
#include <math.h>

// Problem constants (fixed by the dataset)
#define B_    2048
#define V_    2
#define D_    256
#define NTOT  4096            // B_*V_
#define SPLITS 8              // column splits for the fused GEMM+stats kernel
#define CN    (NTOT/SPLITS)   // 512 columns per CTA
#define BM    128
#define BN    128
#define BK    32

#define GAMMA_F   0.9f
#define TEMP_F    0.07f
#define BASET_F   0.07f

// ---------------- device scratch (no allocations allowed) ----------------
__device__ float g_F[NTOT * D_];               // rearranged contrast features [N, D]
__device__ float g_Mp[SPLITS * NTOT];          // per-(split,row) partial max
__device__ float g_Ap[SPLITS * NTOT];          // per-(split,row) partial sum exp (neg)
__device__ float g_Wp[SPLITS * NTOT];          // per-(split,row) partial sum exp*logit (neg)
__device__ float g_SP[NTOT];                   // S[i, pos(i)]  (raw, /T applied)
__device__ float g_M[NTOT];                    // reduced row max
__device__ float g_A[NTOT];                    // reduced row neg exp-sum
__device__ float g_W[NTOT];                    // reduced row neg exp*logit sum

// ---------------- kernel 1: rearrange features -> F[N][D] ----------------
// row n = v*B + b  maps to features[b, v, :]
__global__ void rearrange_kernel(const float* __restrict__ feats) {
    int idx = blockIdx.x * blockDim.x + threadIdx.x;
    if (idx >= NTOT * D_) return;
    int n = idx / D_;
    int d = idx - n * D_;
    int v = n / B_;
    int b = n - v * B_;
    g_F[idx] = feats[(b * V_ + v) * D_ + d];
}

// ---------------- kernel 2: fused GEMM + online row statistics ----------------
// grid: (SPLITS, NTOT/BM), block 256.
// Each CTA: rows [row0, row0+128), columns [split*512, split*512+512) in 4 tiles of 128.
__global__ __launch_bounds__(256, 2) void gemm_stats_kernel() {
    __shared__ float sm[BK * BM + BK * BN];   // 8192 floats = 32KB, reused for reduction
    float* As = sm;                // [BK][BM]
    float* Bs = sm + BK * BM;      // [BK][BN]

    const int tid = threadIdx.x;
    const int tx  = tid & 15;       // 0..15  -> columns tx*8..tx*8+7
    const int ty  = tid >> 4;       // 0..15  -> rows    ty*8..ty*8+7
    const int split = blockIdx.x;
    const int row0  = blockIdx.y * BM;
    const float invT = 1.0f / TEMP_F;

    // online per-row stats for this thread's 8 rows
    float m8[8], A8[8], W8[8];
#pragma unroll
    for (int r = 0; r < 8; r++) { m8[r] = -1e30f; A8[r] = 0.0f; W8[r] = 0.0f; }

    for (int ct = 0; ct < CN / BN; ct++) {
        const int col0 = split * CN + ct * BN;

        float acc[8][8];
#pragma unroll
        for (int r = 0; r < 8; r++)
#pragma unroll
            for (int c = 0; c < 8; c++) acc[r][c] = 0.0f;

        for (int kt = 0; kt < D_; kt += BK) {
            __syncthreads();
            // load A tile (128 rows x 32 k) and B tile (128 cols x 32 k), both as [BK][128]
#pragma unroll
            for (int it = 0; it < 4; it++) {
                int q  = tid + it * 256;       // 0..1023
                int rr = q >> 3;               // 0..127
                int k4 = q & 7;                // 0..7  -> k = k4*4
                float4 va = *(const float4*)&g_F[(row0 + rr) * D_ + kt + k4 * 4];
                As[(k4 * 4 + 0) * BM + rr] = va.x;
                As[(k4 * 4 + 1) * BM + rr] = va.y;
                As[(k4 * 4 + 2) * BM + rr] = va.z;
                As[(k4 * 4 + 3) * BM + rr] = va.w;
                float4 vb = *(const float4*)&g_F[(col0 + rr) * D_ + kt + k4 * 4];
                Bs[(k4 * 4 + 0) * BN + rr] = vb.x;
                Bs[(k4 * 4 + 1) * BN + rr] = vb.y;
                Bs[(k4 * 4 + 2) * BN + rr] = vb.z;
                Bs[(k4 * 4 + 3) * BN + rr] = vb.w;
            }
            __syncthreads();

#pragma unroll
            for (int kk = 0; kk < BK; kk++) {
                float4 a0 = *(const float4*)&As[kk * BM + ty * 8];
                float4 a1 = *(const float4*)&As[kk * BM + ty * 8 + 4];
                float4 b0 = *(const float4*)&Bs[kk * BN + tx * 8];
                float4 b1 = *(const float4*)&Bs[kk * BN + tx * 8 + 4];
                float ar[8] = {a0.x, a0.y, a0.z, a0.w, a1.x, a1.y, a1.z, a1.w};
                float br[8] = {b0.x, b0.y, b0.z, b0.w, b1.x, b1.y, b1.z, b1.w};
#pragma unroll
                for (int r = 0; r < 8; r++)
#pragma unroll
                    for (int c = 0; c < 8; c++)
                        acc[r][c] = fmaf(ar[r], br[c], acc[r][c]);
            }
        }

        // epilogue: online update of (m, A, W) with masks
#pragma unroll
        for (int r = 0; r < 8; r++) {
            int gi   = row0 + ty * 8 + r;
            int posj = (gi + B_) & (NTOT - 1);   // the single positive column
            float s[8];
#pragma unroll
            for (int c = 0; c < 8; c++) s[c] = acc[r][c] * invT;

            float tmax = -1e30f;
#pragma unroll
            for (int c = 0; c < 8; c++) tmax = fmaxf(tmax, s[c]);  // max includes pos & diag

            float mOld = m8[r];
            float mNew = fmaxf(mOld, tmax);
            float sc   = __expf(mOld - mNew);       // exp(-huge)=0 on first tile
            float Aold = A8[r];
            A8[r] = Aold * sc;
            W8[r] = sc * (W8[r] + (mOld - mNew) * Aold);
            m8[r] = mNew;

#pragma unroll
            for (int c = 0; c < 8; c++) {
                int gj = col0 + tx * 8 + c;
                if (gj == posj) {
                    g_SP[gi] = s[c];                 // exactly one writer grid-wide
                } else {
                    float e = __expf(s[c] - mNew);   // negatives include the diagonal
                    A8[r] += e;
                    W8[r] += e * (s[c] - mNew);
                }
            }
        }
    }

    // CTA-level merge across the 16 tx-threads that share each row
    __syncthreads();
    float* redM = sm;             // [128][16]
    float* redA = sm + 2048;      // [128][16]
    float* redW = sm + 4096;      // [128][16]
#pragma unroll
    for (int r = 0; r < 8; r++) {
        int lr = ty * 8 + r;
        redM[lr * 16 + tx] = m8[r];
        redA[lr * 16 + tx] = A8[r];
        redW[lr * 16 + tx] = W8[r];
    }
    __syncthreads();
    if (tid < BM) {
        int lr = tid;
        float mm = -1e30f, aa = 0.0f, ww = 0.0f;
#pragma unroll
        for (int t = 0; t < 16; t++) {
            float m2 = redM[lr * 16 + t];
            float a2 = redA[lr * 16 + t];
            float w2 = redW[lr * 16 + t];
            float mN = fmaxf(mm, m2);
            float c1 = __expf(mm - mN);
            float c2 = __expf(m2 - mN);
            ww = c1 * (ww + (mm - mN) * aa) + c2 * (w2 + (m2 - mN) * a2);
            aa = c1 * aa + c2 * a2;
            mm = mN;
        }
        int gi = row0 + lr;
        g_Mp[split * NTOT + gi] = mm;
        g_Ap[split * NTOT + gi] = aa;
        g_Wp[split * NTOT + gi] = ww;
    }
}

// ---------------- kernel 3: combine column-split partials per row ----------------
__global__ void combine_kernel() {
    int i = blockIdx.x * blockDim.x + threadIdx.x;
    if (i >= NTOT) return;
    float mm = -1e30f, aa = 0.0f, ww = 0.0f;
#pragma unroll
    for (int s = 0; s < SPLITS; s++) {
        float m2 = g_Mp[s * NTOT + i];
        float a2 = g_Ap[s * NTOT + i];
        float w2 = g_Wp[s * NTOT + i];
        float mN = fmaxf(mm, m2);
        float c1 = __expf(mm - mN);
        float c2 = __expf(m2 - mN);
        ww = c1 * (ww + (mm - mN) * aa) + c2 * (w2 + (m2 - mN) * a2);
        aa = c1 * aa + c2 * a2;
        mm = mN;
    }
    g_M[i] = mm;
    g_A[i] = aa;
    g_W[i] = ww;
}

// ---------------- kernel 4: per-row loss + scalar reduction ----------------
__global__ void loss_kernel(const int* __restrict__ index,
                            const float* __restrict__ u,
                            float* __restrict__ out) {
    __shared__ float red[256];
    const float factor = TEMP_F / BASET_F;
    float acc = 0.0f;
    for (int i = threadIdx.x; i < NTOT; i += 256) {
        int b = i & (B_ - 1);                     // i % B
        float u_new = (1.0f - GAMMA_F) * u[index[b]] + GAMMA_F * g_A[b];
        float t = g_W[i] / u_new;
        float lpos = g_SP[i] - g_M[i];
        acc += -factor * (lpos - t);
    }
    red[threadIdx.x] = acc;
    __syncthreads();
#pragma unroll
    for (int s = 128; s > 0; s >>= 1) {
        if (threadIdx.x < s) red[threadIdx.x] += red[threadIdx.x + s];
        __syncthreads();
    }
    if (threadIdx.x == 0) out[0] = red[0] / (float)NTOT;
}

// ---------------- launch ----------------
extern "C" void kernel_launch(void* const* d_in, const int* in_sizes, int n_in,
                              void* d_out, int out_size) {
    const int*   d_index = nullptr;
    const float* d_feats = nullptr;
    const float* d_u     = nullptr;
    for (int i = 0; i < n_in; i++) {
        if (in_sizes[i] == B_)                 d_index = (const int*)d_in[i];
        else if (in_sizes[i] == B_ * V_ * D_)  d_feats = (const float*)d_in[i];
        else                                   d_u     = (const float*)d_in[i];
    }
    float* out = (float*)d_out;

    rearrange_kernel<<<(NTOT * D_ + 255) / 256, 256>>>(d_feats);
    gemm_stats_kernel<<<dim3(SPLITS, NTOT / BM), 256>>>();
    combine_kernel<<<(NTOT + 255) / 256, 256>>>();
    loss_kernel<<<1, 256>>>(d_index, d_u, out);
}

// round 4
// speedup vs baseline: 2.0708x; 2.0708x over previous
#include <cuda_runtime.h>
#include <cuda_bf16.h>
#include <stdint.h>

// ---------------- problem constants ----------------
#define B_    2048
#define V_    2
#define D_    256
#define NTOT  4096
#define CT_   32              // column tiles of 128
#define GAMMA_F   0.9f
#define TEMP_F    0.07f
#define BASET_F   0.07f

// ---------------- device scratch ----------------
__device__ __nv_bfloat16 g_Fhi[NTOT * D_];
__device__ __nv_bfloat16 g_Flo[NTOT * D_];
__device__ float g_Mp[CT_ * NTOT];
__device__ float g_Ap[CT_ * NTOT];
__device__ float g_Wp[CT_ * NTOT];
__device__ float g_SP[NTOT];
__device__ float g_M[NTOT];
__device__ float g_A[NTOT];
__device__ float g_W[NTOT];
__device__ float g_Lp[16];

// ---------------- helpers ----------------
__device__ __forceinline__ uint32_t smem_u32(const void* p) {
    uint32_t a;
    asm("{ .reg .u64 t; cvta.to.shared.u64 t, %1; cvt.u32.u64 %0, t; }" : "=r"(a) : "l"(p));
    return a;
}
__device__ __forceinline__ uint32_t sw128(uint32_t off) {
    return off ^ ((off >> 3) & 0x70);
}
__device__ __forceinline__ void ldsm_x4(uint32_t* r, uint32_t addr) {
    asm volatile("ldmatrix.sync.aligned.m8n8.x4.shared.b16 {%0,%1,%2,%3}, [%4];"
                 : "=r"(r[0]), "=r"(r[1]), "=r"(r[2]), "=r"(r[3]) : "r"(addr));
}
__device__ __forceinline__ void mma_bf16(float* c, const uint32_t* a, uint32_t b0, uint32_t b1) {
    asm volatile("mma.sync.aligned.m16n8k16.row.col.f32.bf16.bf16.f32 "
                 "{%0,%1,%2,%3}, {%4,%5,%6,%7}, {%8,%9}, {%0,%1,%2,%3};"
                 : "+f"(c[0]), "+f"(c[1]), "+f"(c[2]), "+f"(c[3])
                 : "r"(a[0]), "r"(a[1]), "r"(a[2]), "r"(a[3]), "r"(b0), "r"(b1));
}

// ---------------- kernel 1: rearrange + bf16 hi/lo split ----------------
__global__ void prep_kernel(const float* __restrict__ feats) {
    int q = blockIdx.x * 256 + threadIdx.x;       // quad index, grid sized exactly
    int e = q * 4;
    int n = e >> 8;
    int d = e & 255;
    int v = n >> 11;
    int b = n & 2047;
    float4 f = *(const float4*)&feats[((b << 1) | v) * D_ + d];
    __nv_bfloat16 h0 = __float2bfloat16(f.x);
    __nv_bfloat16 h1 = __float2bfloat16(f.y);
    __nv_bfloat16 h2 = __float2bfloat16(f.z);
    __nv_bfloat16 h3 = __float2bfloat16(f.w);
    __nv_bfloat16 l0 = __float2bfloat16(f.x - __bfloat162float(h0));
    __nv_bfloat16 l1 = __float2bfloat16(f.y - __bfloat162float(h1));
    __nv_bfloat16 l2 = __float2bfloat16(f.z - __bfloat162float(h2));
    __nv_bfloat16 l3 = __float2bfloat16(f.w - __bfloat162float(h3));
    uint2 hp, lp;
    hp.x = ((uint32_t)__bfloat16_as_ushort(h1) << 16) | __bfloat16_as_ushort(h0);
    hp.y = ((uint32_t)__bfloat16_as_ushort(h3) << 16) | __bfloat16_as_ushort(h2);
    lp.x = ((uint32_t)__bfloat16_as_ushort(l1) << 16) | __bfloat16_as_ushort(l0);
    lp.y = ((uint32_t)__bfloat16_as_ushort(l3) << 16) | __bfloat16_as_ushort(l2);
    *(uint2*)&g_Fhi[e] = hp;
    *(uint2*)&g_Flo[e] = lp;
}

// ---------------- kernel 2: mma.sync GEMM + fused row stats ----------------
// CTA 128x128, 8 warps as 2(M) x 4(N), warp tile 64x32.
// K staged in 4 chunks of 64; smem holds Ahi/Alo/Bhi/Blo (16KB each).
#define OFF_AHI 0
#define OFF_ALO 16384
#define OFF_BHI 32768
#define OFF_BLO 49152
#define SMEM_BYTES 65536

__global__ void __launch_bounds__(256, 2) gemm_stats_kernel() {
    extern __shared__ char smem[];
    const uint32_t sb = smem_u32(smem);
    const int tid  = threadIdx.x;
    const int lane = tid & 31;
    const int wid  = tid >> 5;
    const int wm   = wid & 1;       // M half (64 rows)
    const int wn   = wid >> 1;      // N quarter (32 cols)
    const int row0 = blockIdx.y * 128;
    const int col0 = blockIdx.x * 128;

    float acc[4][4][4];
#pragma unroll
    for (int mi = 0; mi < 4; mi++)
#pragma unroll
        for (int nj = 0; nj < 4; nj++)
#pragma unroll
            for (int c = 0; c < 4; c++) acc[mi][nj][c] = 0.0f;

    // precomputed ldmatrix base coords for this lane
    const int arow  = wm * 64 + (lane & 7) + ((lane >> 3) & 1) * 8;
    const int akc0  = (lane >> 4) * 8;                // k sub-offset for A
    const int brow  = wn * 32 + (lane & 7) + (lane >> 4) * 8;
    const int bkc0  = ((lane >> 3) & 1) * 8;          // k sub-offset for B

    for (int kc = 0; kc < 4; kc++) {
        __syncthreads();
        // stage Ahi/Alo (rows row0+0..127) and Bhi/Blo (rows col0+0..127), 64 k-cols
#pragma unroll
        for (int it = 0; it < 4; it++) {
            int q = tid + it * 256;
            int r = q >> 3, c = q & 7;
            uint32_t sw = sw128((uint32_t)(r * 128 + c * 16));
            int srcA = (row0 + r) * D_ + kc * 64 + c * 8;
            int srcB = (col0 + r) * D_ + kc * 64 + c * 8;
            *(uint4*)(smem + OFF_AHI + sw) = *(const uint4*)&g_Fhi[srcA];
            *(uint4*)(smem + OFF_ALO + sw) = *(const uint4*)&g_Flo[srcA];
            *(uint4*)(smem + OFF_BHI + sw) = *(const uint4*)&g_Fhi[srcB];
            *(uint4*)(smem + OFF_BLO + sw) = *(const uint4*)&g_Flo[srcB];
        }
        __syncthreads();

#pragma unroll
        for (int p = 0; p < 3; p++) {
            const uint32_t aoff = (p < 2) ? OFF_AHI : OFF_ALO;
            const uint32_t boff = (p == 1) ? OFF_BLO : OFF_BHI;
#pragma unroll
            for (int ks = 0; ks < 4; ks++) {
                uint32_t a[4][4], b[2][4];
                const int akc = ks * 16 + akc0;
                const int bkc = ks * 16 + bkc0;
#pragma unroll
                for (int mi = 0; mi < 4; mi++)
                    ldsm_x4(a[mi], sb + aoff + sw128((uint32_t)((arow + mi * 16) * 128 + akc * 2)));
#pragma unroll
                for (int bi = 0; bi < 2; bi++)
                    ldsm_x4(b[bi], sb + boff + sw128((uint32_t)((brow + bi * 16) * 128 + bkc * 2)));
#pragma unroll
                for (int mi = 0; mi < 4; mi++) {
#pragma unroll
                    for (int nj = 0; nj < 4; nj++) {
                        uint32_t b0 = (nj & 1) ? b[nj >> 1][2] : b[nj >> 1][0];
                        uint32_t b1 = (nj & 1) ? b[nj >> 1][3] : b[nj >> 1][1];
                        mma_bf16(acc[mi][nj], a[mi], b0, b1);
                    }
                }
            }
        }
    }

    // ---------------- epilogue: row stats from register fragments ----------------
    __syncthreads();
    float* redm = (float*)smem;        // [128][4]
    float* reda = redm + 512;
    float* redw = reda + 512;
    const float invT = 1.0f / TEMP_F;

#pragma unroll
    for (int mi = 0; mi < 4; mi++) {
#pragma unroll
        for (int h = 0; h < 2; h++) {
            int lr = wm * 64 + mi * 16 + h * 8 + (lane >> 2);
            int gi = row0 + lr;
            int posj = (gi + B_) & (NTOT - 1);
            float s[8];
#pragma unroll
            for (int nj = 0; nj < 4; nj++) {
                s[nj * 2]     = acc[mi][nj][h * 2]     * invT;
                s[nj * 2 + 1] = acc[mi][nj][h * 2 + 1] * invT;
            }
            float m = s[0];
#pragma unroll
            for (int i2 = 1; i2 < 8; i2++) m = fmaxf(m, s[i2]);
            m = fmaxf(m, __shfl_xor_sync(0xffffffffu, m, 1));
            m = fmaxf(m, __shfl_xor_sync(0xffffffffu, m, 2));
            float A = 0.0f, W = 0.0f;
#pragma unroll
            for (int nj = 0; nj < 4; nj++) {
#pragma unroll
                for (int c = 0; c < 2; c++) {
                    int gj = col0 + wn * 32 + nj * 8 + (lane & 3) * 2 + c;
                    float v = s[nj * 2 + c];
                    if (gj == posj) {
                        g_SP[gi] = v;               // unique writer grid-wide
                    } else {
                        float e = __expf(v - m);    // diagonal stays a negative
                        A += e;
                        W += e * (v - m);
                    }
                }
            }
            A += __shfl_xor_sync(0xffffffffu, A, 1);
            A += __shfl_xor_sync(0xffffffffu, A, 2);
            W += __shfl_xor_sync(0xffffffffu, W, 1);
            W += __shfl_xor_sync(0xffffffffu, W, 2);
            if ((lane & 3) == 0) {
                redm[lr * 4 + wn] = m;
                reda[lr * 4 + wn] = A;
                redw[lr * 4 + wn] = W;
            }
        }
    }
    __syncthreads();
    if (tid < 128) {
        float mm = redm[tid * 4], aa = reda[tid * 4], ww = redw[tid * 4];
#pragma unroll
        for (int t = 1; t < 4; t++) {
            float m2 = redm[tid * 4 + t];
            float a2 = reda[tid * 4 + t];
            float w2 = redw[tid * 4 + t];
            float mN = fmaxf(mm, m2);
            float c1 = __expf(mm - mN);
            float c2 = __expf(m2 - mN);
            ww = c1 * (ww + (mm - mN) * aa) + c2 * (w2 + (m2 - mN) * a2);
            aa = c1 * aa + c2 * a2;
            mm = mN;
        }
        g_Mp[blockIdx.x * NTOT + row0 + tid] = mm;
        g_Ap[blockIdx.x * NTOT + row0 + tid] = aa;
        g_Wp[blockIdx.x * NTOT + row0 + tid] = ww;
    }
}

// ---------------- kernel 3: combine column-tile partials ----------------
__global__ void combine_kernel() {
    int i = blockIdx.x * 256 + threadIdx.x;
    if (i >= NTOT) return;
    float mm = -1e30f, aa = 0.0f, ww = 0.0f;
#pragma unroll
    for (int s = 0; s < CT_; s++) {
        float m2 = g_Mp[s * NTOT + i];
        float a2 = g_Ap[s * NTOT + i];
        float w2 = g_Wp[s * NTOT + i];
        float mN = fmaxf(mm, m2);
        float c1 = __expf(mm - mN);
        float c2 = __expf(m2 - mN);
        ww = c1 * (ww + (mm - mN) * aa) + c2 * (w2 + (m2 - mN) * a2);
        aa = c1 * aa + c2 * a2;
        mm = mN;
    }
    g_M[i] = mm;
    g_A[i] = aa;
    g_W[i] = ww;
}

// ---------------- kernel 4: per-row loss partials (deterministic) ----------------
__global__ void loss_partial_kernel(const int* __restrict__ index,
                                    const float* __restrict__ u) {
    __shared__ float red[8];
    int i = blockIdx.x * 256 + threadIdx.x;
    int b = i & (B_ - 1);                     // i % B
    float u_new = (1.0f - GAMMA_F) * u[index[b]] + GAMMA_F * g_A[b];
    float val = -(TEMP_F / BASET_F) * ((g_SP[i] - g_M[i]) - g_W[i] / u_new) * (1.0f / (float)NTOT);
#pragma unroll
    for (int o = 16; o; o >>= 1) val += __shfl_down_sync(0xffffffffu, val, o);
    if ((threadIdx.x & 31) == 0) red[threadIdx.x >> 5] = val;
    __syncthreads();
    if (threadIdx.x < 8) {
        float v = red[threadIdx.x];
#pragma unroll
        for (int o = 4; o; o >>= 1) v += __shfl_down_sync(0xffu, v, o);
        if (threadIdx.x == 0) g_Lp[blockIdx.x] = v;
    }
}

__global__ void loss_final_kernel(float* __restrict__ out) {
    float v = (threadIdx.x < 16) ? g_Lp[threadIdx.x] : 0.0f;
#pragma unroll
    for (int o = 8; o; o >>= 1) v += __shfl_down_sync(0xffffffffu, v, o);
    if (threadIdx.x == 0) out[0] = v;
}

// ---------------- launch ----------------
extern "C" void kernel_launch(void* const* d_in, const int* in_sizes, int n_in,
                              void* d_out, int out_size) {
    const int*   d_index = nullptr;
    const float* d_feats = nullptr;
    const float* d_u     = nullptr;
    for (int i = 0; i < n_in; i++) {
        if (in_sizes[i] == B_)                 d_index = (const int*)d_in[i];
        else if (in_sizes[i] == B_ * V_ * D_)  d_feats = (const float*)d_in[i];
        else                                   d_u     = (const float*)d_in[i];
    }
    float* out = (float*)d_out;

    cudaFuncSetAttribute(gemm_stats_kernel,
                         cudaFuncAttributeMaxDynamicSharedMemorySize, SMEM_BYTES);

    prep_kernel<<<NTOT * D_ / 4 / 256, 256>>>(d_feats);
    gemm_stats_kernel<<<dim3(CT_, NTOT / 128), 256, SMEM_BYTES>>>();
    combine_kernel<<<NTOT / 256, 256>>>();
    loss_partial_kernel<<<NTOT / 256, 256>>>(d_index, d_u);
    loss_final_kernel<<<1, 32>>>(out);
}

// round 5
// speedup vs baseline: 3.0110x; 1.4540x over previous
#include <cuda_runtime.h>
#include <cuda_bf16.h>
#include <stdint.h>

// ---------------- problem constants ----------------
#define B_    2048
#define V_    2
#define D_    256
#define NTOT  4096
#define NB_   32              // 128-wide blocks per dimension
#define NTILES 528            // NB*(NB+1)/2 upper-triangular tiles
#define GAMMA_F   0.9f
#define TEMP_F    0.07f
#define BASET_F   0.07f

// ---------------- device scratch ----------------
__device__ __nv_bfloat16 g_Fhi[NTOT * D_];
__device__ __nv_bfloat16 g_Flo[NTOT * D_];
__device__ float g_Mp[NB_ * NTOT];
__device__ float g_Ap[NB_ * NTOT];
__device__ float g_Wp[NB_ * NTOT];
__device__ float g_SP[NTOT];
__device__ float g_M[NTOT];
__device__ float g_A[NTOT];
__device__ float g_W[NTOT];
__device__ float g_Lp[16];

// ---------------- helpers ----------------
__device__ __forceinline__ uint32_t smem_u32(const void* p) {
    uint32_t a;
    asm("{ .reg .u64 t; cvta.to.shared.u64 t, %1; cvt.u32.u64 %0, t; }" : "=r"(a) : "l"(p));
    return a;
}
__device__ __forceinline__ uint32_t sw128(uint32_t off) {
    return off ^ ((off >> 3) & 0x70);
}
__device__ __forceinline__ void ldsm_x4(uint32_t* r, uint32_t addr) {
    asm volatile("ldmatrix.sync.aligned.m8n8.x4.shared.b16 {%0,%1,%2,%3}, [%4];"
                 : "=r"(r[0]), "=r"(r[1]), "=r"(r[2]), "=r"(r[3]) : "r"(addr));
}
__device__ __forceinline__ void mma_bf16(float* c, const uint32_t* a, uint32_t b0, uint32_t b1) {
    asm volatile("mma.sync.aligned.m16n8k16.row.col.f32.bf16.bf16.f32 "
                 "{%0,%1,%2,%3}, {%4,%5,%6,%7}, {%8,%9}, {%0,%1,%2,%3};"
                 : "+f"(c[0]), "+f"(c[1]), "+f"(c[2]), "+f"(c[3])
                 : "r"(a[0]), "r"(a[1]), "r"(a[2]), "r"(a[3]), "r"(b0), "r"(b1));
}

// ---------------- kernel 1: rearrange + bf16 hi/lo split ----------------
__global__ void prep_kernel(const float* __restrict__ feats) {
    int q = blockIdx.x * 256 + threadIdx.x;       // quad index, grid sized exactly
    int e = q * 4;
    int n = e >> 8;
    int d = e & 255;
    int v = n >> 11;
    int b = n & 2047;
    float4 f = *(const float4*)&feats[((b << 1) | v) * D_ + d];
    __nv_bfloat16 h0 = __float2bfloat16(f.x);
    __nv_bfloat16 h1 = __float2bfloat16(f.y);
    __nv_bfloat16 h2 = __float2bfloat16(f.z);
    __nv_bfloat16 h3 = __float2bfloat16(f.w);
    __nv_bfloat16 l0 = __float2bfloat16(f.x - __bfloat162float(h0));
    __nv_bfloat16 l1 = __float2bfloat16(f.y - __bfloat162float(h1));
    __nv_bfloat16 l2 = __float2bfloat16(f.z - __bfloat162float(h2));
    __nv_bfloat16 l3 = __float2bfloat16(f.w - __bfloat162float(h3));
    uint2 hp, lp;
    hp.x = ((uint32_t)__bfloat16_as_ushort(h1) << 16) | __bfloat16_as_ushort(h0);
    hp.y = ((uint32_t)__bfloat16_as_ushort(h3) << 16) | __bfloat16_as_ushort(h2);
    lp.x = ((uint32_t)__bfloat16_as_ushort(l1) << 16) | __bfloat16_as_ushort(l0);
    lp.y = ((uint32_t)__bfloat16_as_ushort(l3) << 16) | __bfloat16_as_ushort(l2);
    *(uint2*)&g_Fhi[e] = hp;
    *(uint2*)&g_Flo[e] = lp;
}

// ---------------- kernel 2: symmetric-tile mma.sync GEMM + fused stats ----------------
// Only diagonal+upper tiles (bi <= bj). Off-diagonal tiles emit BOTH row-block
// partials (rows of bi over cols of bj) and transposed col-block partials
// (rows of bj over cols of bi), exploiting S = S^T.
#define OFF_AHI 0
#define OFF_ALO 16384
#define OFF_BHI 32768
#define OFF_BLO 49152
#define SMEM_BYTES 65536

__global__ void __launch_bounds__(256, 2) gemm_stats_kernel() {
    extern __shared__ char smem[];
    const uint32_t sb = smem_u32(smem);
    const int tid  = threadIdx.x;
    const int lane = tid & 31;
    const int wid  = tid >> 5;
    const int wm   = wid & 1;       // M half (64 rows)
    const int wn   = wid >> 1;      // N quarter (32 cols)

    // decode upper-triangular tile (bi, bj), bi <= bj
    int bi = 0, rem = blockIdx.x;
    while (rem >= (NB_ - bi)) { rem -= (NB_ - bi); bi++; }
    const int bj = bi + rem;
    const int row0 = bi * 128;
    const int col0 = bj * 128;

    float acc[4][4][4];
#pragma unroll
    for (int mi = 0; mi < 4; mi++)
#pragma unroll
        for (int nj = 0; nj < 4; nj++)
#pragma unroll
            for (int c = 0; c < 4; c++) acc[mi][nj][c] = 0.0f;

    const int arow  = wm * 64 + (lane & 7) + ((lane >> 3) & 1) * 8;
    const int akc0  = (lane >> 4) * 8;
    const int brow  = wn * 32 + (lane & 7) + (lane >> 4) * 8;
    const int bkc0  = ((lane >> 3) & 1) * 8;

    for (int kc = 0; kc < 4; kc++) {
        __syncthreads();
#pragma unroll
        for (int it = 0; it < 4; it++) {
            int q = tid + it * 256;
            int r = q >> 3, c = q & 7;
            uint32_t sw = sw128((uint32_t)(r * 128 + c * 16));
            int srcA = (row0 + r) * D_ + kc * 64 + c * 8;
            int srcB = (col0 + r) * D_ + kc * 64 + c * 8;
            *(uint4*)(smem + OFF_AHI + sw) = *(const uint4*)&g_Fhi[srcA];
            *(uint4*)(smem + OFF_ALO + sw) = *(const uint4*)&g_Flo[srcA];
            *(uint4*)(smem + OFF_BHI + sw) = *(const uint4*)&g_Fhi[srcB];
            *(uint4*)(smem + OFF_BLO + sw) = *(const uint4*)&g_Flo[srcB];
        }
        __syncthreads();

#pragma unroll
        for (int p = 0; p < 3; p++) {
            const uint32_t aoff = (p < 2) ? OFF_AHI : OFF_ALO;
            const uint32_t boff = (p == 1) ? OFF_BLO : OFF_BHI;
#pragma unroll
            for (int ks = 0; ks < 4; ks++) {
                uint32_t a[4][4], b[2][4];
                const int akc = ks * 16 + akc0;
                const int bkc = ks * 16 + bkc0;
#pragma unroll
                for (int mi = 0; mi < 4; mi++)
                    ldsm_x4(a[mi], sb + aoff + sw128((uint32_t)((arow + mi * 16) * 128 + akc * 2)));
#pragma unroll
                for (int bi2 = 0; bi2 < 2; bi2++)
                    ldsm_x4(b[bi2], sb + boff + sw128((uint32_t)((brow + bi2 * 16) * 128 + bkc * 2)));
#pragma unroll
                for (int mi = 0; mi < 4; mi++) {
#pragma unroll
                    for (int nj = 0; nj < 4; nj++) {
                        uint32_t b0 = (nj & 1) ? b[nj >> 1][2] : b[nj >> 1][0];
                        uint32_t b1 = (nj & 1) ? b[nj >> 1][3] : b[nj >> 1][1];
                        mma_bf16(acc[mi][nj], a[mi], b0, b1);
                    }
                }
            }
        }
    }

    // ---------------- epilogue ----------------
    __syncthreads();
    float* redm = (float*)smem;          // [128][4] row partials
    float* reda = redm + 512;
    float* redw = reda + 512;
    float* colm = redw + 512;            // [128][2] col partials
    float* cola = colm + 256;
    float* colw = cola + 256;
    const float invT = 1.0f / TEMP_F;

    // --- row pass: stats for rows of block bi over cols of block bj ---
#pragma unroll
    for (int mi = 0; mi < 4; mi++) {
#pragma unroll
        for (int h = 0; h < 2; h++) {
            int lr = wm * 64 + mi * 16 + h * 8 + (lane >> 2);
            int gi = row0 + lr;
            int posj = (gi + B_) & (NTOT - 1);
            float s[8];
#pragma unroll
            for (int nj = 0; nj < 4; nj++) {
                s[nj * 2]     = acc[mi][nj][h * 2]     * invT;
                s[nj * 2 + 1] = acc[mi][nj][h * 2 + 1] * invT;
            }
            float m = s[0];
#pragma unroll
            for (int i2 = 1; i2 < 8; i2++) m = fmaxf(m, s[i2]);
            m = fmaxf(m, __shfl_xor_sync(0xffffffffu, m, 1));
            m = fmaxf(m, __shfl_xor_sync(0xffffffffu, m, 2));
            float A = 0.0f, W = 0.0f;
#pragma unroll
            for (int nj = 0; nj < 4; nj++) {
#pragma unroll
                for (int c = 0; c < 2; c++) {
                    int gj = col0 + wn * 32 + nj * 8 + (lane & 3) * 2 + c;
                    float v = s[nj * 2 + c];
                    if (gj == posj) {
                        g_SP[gi] = v;
                    } else {
                        float e = __expf(v - m);
                        A += e;
                        W += e * (v - m);
                    }
                }
            }
            A += __shfl_xor_sync(0xffffffffu, A, 1);
            A += __shfl_xor_sync(0xffffffffu, A, 2);
            W += __shfl_xor_sync(0xffffffffu, W, 1);
            W += __shfl_xor_sync(0xffffffffu, W, 2);
            if ((lane & 3) == 0) {
                redm[lr * 4 + wn] = m;
                reda[lr * 4 + wn] = A;
                redw[lr * 4 + wn] = W;
            }
        }
    }

    // --- col pass (off-diagonal only): stats for rows of block bj over cols of block bi ---
    if (bi != bj) {
#pragma unroll
        for (int nj = 0; nj < 4; nj++) {
#pragma unroll
            for (int cb = 0; cb < 2; cb++) {
                int cid = wn * 32 + nj * 8 + (lane & 3) * 2 + cb;   // local col
                int gj = col0 + cid;
                int posi = (gj + B_) & (NTOT - 1);
                float sv[8];
#pragma unroll
                for (int mi = 0; mi < 4; mi++) {
                    sv[mi * 2]     = acc[mi][nj][cb]     * invT;
                    sv[mi * 2 + 1] = acc[mi][nj][2 + cb] * invT;
                }
                float m = sv[0];
#pragma unroll
                for (int i2 = 1; i2 < 8; i2++) m = fmaxf(m, sv[i2]);
                m = fmaxf(m, __shfl_xor_sync(0xffffffffu, m, 4));
                m = fmaxf(m, __shfl_xor_sync(0xffffffffu, m, 8));
                m = fmaxf(m, __shfl_xor_sync(0xffffffffu, m, 16));
                float A = 0.0f, W = 0.0f;
#pragma unroll
                for (int mi = 0; mi < 4; mi++) {
#pragma unroll
                    for (int h = 0; h < 2; h++) {
                        int gi = row0 + wm * 64 + mi * 16 + h * 8 + (lane >> 2);
                        float v = sv[mi * 2 + h];
                        if (gi == posi) {
                            g_SP[gj] = v;          // S symmetric: S[gi,gj]==S[gj,gi]
                        } else {
                            float e = __expf(v - m);
                            A += e;
                            W += e * (v - m);
                        }
                    }
                }
                A += __shfl_xor_sync(0xffffffffu, A, 4);
                A += __shfl_xor_sync(0xffffffffu, A, 8);
                A += __shfl_xor_sync(0xffffffffu, A, 16);
                W += __shfl_xor_sync(0xffffffffu, W, 4);
                W += __shfl_xor_sync(0xffffffffu, W, 8);
                W += __shfl_xor_sync(0xffffffffu, W, 16);
                if ((lane >> 2) == 0) {
                    colm[cid * 2 + wm] = m;
                    cola[cid * 2 + wm] = A;
                    colw[cid * 2 + wm] = W;
                }
            }
        }
    }

    __syncthreads();
    if (tid < 128) {
        // row-block partial -> slot [bj]
        float mm = redm[tid * 4], aa = reda[tid * 4], ww = redw[tid * 4];
#pragma unroll
        for (int t = 1; t < 4; t++) {
            float m2 = redm[tid * 4 + t];
            float a2 = reda[tid * 4 + t];
            float w2 = redw[tid * 4 + t];
            float mN = fmaxf(mm, m2);
            float c1 = __expf(mm - mN);
            float c2 = __expf(m2 - mN);
            ww = c1 * (ww + (mm - mN) * aa) + c2 * (w2 + (m2 - mN) * a2);
            aa = c1 * aa + c2 * a2;
            mm = mN;
        }
        g_Mp[bj * NTOT + row0 + tid] = mm;
        g_Ap[bj * NTOT + row0 + tid] = aa;
        g_Wp[bj * NTOT + row0 + tid] = ww;
    } else if (bi != bj && tid < 256) {
        // col-block (transposed) partial -> slot [bi]
        int cid = tid - 128;
        float m1 = colm[cid * 2],     a1 = cola[cid * 2],     w1 = colw[cid * 2];
        float m2 = colm[cid * 2 + 1], a2 = cola[cid * 2 + 1], w2 = colw[cid * 2 + 1];
        float mN = fmaxf(m1, m2);
        float c1 = __expf(m1 - mN), c2 = __expf(m2 - mN);
        float ww = c1 * (w1 + (m1 - mN) * a1) + c2 * (w2 + (m2 - mN) * a2);
        float aa = c1 * a1 + c2 * a2;
        g_Mp[bi * NTOT + col0 + cid] = mN;
        g_Ap[bi * NTOT + col0 + cid] = aa;
        g_Wp[bi * NTOT + col0 + cid] = ww;
    }
}

// ---------------- kernel 3: combine column-block partials ----------------
__global__ void combine_kernel() {
    int i = blockIdx.x * 256 + threadIdx.x;
    if (i >= NTOT) return;
    float mm = -1e30f, aa = 0.0f, ww = 0.0f;
#pragma unroll
    for (int s = 0; s < NB_; s++) {
        float m2 = g_Mp[s * NTOT + i];
        float a2 = g_Ap[s * NTOT + i];
        float w2 = g_Wp[s * NTOT + i];
        float mN = fmaxf(mm, m2);
        float c1 = __expf(mm - mN);
        float c2 = __expf(m2 - mN);
        ww = c1 * (ww + (mm - mN) * aa) + c2 * (w2 + (m2 - mN) * a2);
        aa = c1 * aa + c2 * a2;
        mm = mN;
    }
    g_M[i] = mm;
    g_A[i] = aa;
    g_W[i] = ww;
}

// ---------------- kernel 4: per-row loss partials (deterministic) ----------------
__global__ void loss_partial_kernel(const int* __restrict__ index,
                                    const float* __restrict__ u) {
    __shared__ float red[8];
    int i = blockIdx.x * 256 + threadIdx.x;
    int b = i & (B_ - 1);
    float u_new = (1.0f - GAMMA_F) * u[index[b]] + GAMMA_F * g_A[b];
    float val = -(TEMP_F / BASET_F) * ((g_SP[i] - g_M[i]) - g_W[i] / u_new) * (1.0f / (float)NTOT);
#pragma unroll
    for (int o = 16; o; o >>= 1) val += __shfl_down_sync(0xffffffffu, val, o);
    if ((threadIdx.x & 31) == 0) red[threadIdx.x >> 5] = val;
    __syncthreads();
    if (threadIdx.x < 8) {
        float v = red[threadIdx.x];
#pragma unroll
        for (int o = 4; o; o >>= 1) v += __shfl_down_sync(0xffu, v, o);
        if (threadIdx.x == 0) g_Lp[blockIdx.x] = v;
    }
}

__global__ void loss_final_kernel(float* __restrict__ out) {
    float v = (threadIdx.x < 16) ? g_Lp[threadIdx.x] : 0.0f;
#pragma unroll
    for (int o = 8; o; o >>= 1) v += __shfl_down_sync(0xffffffffu, v, o);
    if (threadIdx.x == 0) out[0] = v;
}

// ---------------- launch ----------------
extern "C" void kernel_launch(void* const* d_in, const int* in_sizes, int n_in,
                              void* d_out, int out_size) {
    const int*   d_index = nullptr;
    const float* d_feats = nullptr;
    const float* d_u     = nullptr;
    for (int i = 0; i < n_in; i++) {
        if (in_sizes[i] == B_)                 d_index = (const int*)d_in[i];
        else if (in_sizes[i] == B_ * V_ * D_)  d_feats = (const float*)d_in[i];
        else                                   d_u     = (const float*)d_in[i];
    }
    float* out = (float*)d_out;

    cudaFuncSetAttribute(gemm_stats_kernel,
                         cudaFuncAttributeMaxDynamicSharedMemorySize, SMEM_BYTES);

    prep_kernel<<<NTOT * D_ / 4 / 256, 256>>>(d_feats);
    gemm_stats_kernel<<<NTILES, 256, SMEM_BYTES>>>();
    combine_kernel<<<NTOT / 256, 256>>>();
    loss_partial_kernel<<<NTOT / 256, 256>>>(d_index, d_u);
    loss_final_kernel<<<1, 32>>>(out);
}

// round 6
// speedup vs baseline: 3.7544x; 1.2469x over previous
#include <cuda_runtime.h>
#include <cuda_bf16.h>
#include <stdint.h>

// ---------------- problem constants ----------------
#define B_    2048
#define V_    2
#define D_    256
#define NTOT  4096
#define NB_   32              // 128-wide blocks per dimension
#define NTILES 528            // NB*(NB+1)/2 upper-triangular tiles
#define GAMMA_F   0.9f
#define TEMP_F    0.07f
#define BASET_F   0.07f

// ---------------- device scratch ----------------
__device__ __nv_bfloat16 g_Fhi[NTOT * D_];
__device__ __nv_bfloat16 g_Flo[NTOT * D_];
__device__ float g_Mp[NB_ * NTOT];
__device__ float g_Ap[NB_ * NTOT];
__device__ float g_Wp[NB_ * NTOT];
__device__ float g_SP[NTOT];
__device__ float g_Lp[8];

// ---------------- helpers ----------------
__device__ __forceinline__ uint32_t smem_u32(const void* p) {
    uint32_t a;
    asm("{ .reg .u64 t; cvta.to.shared.u64 t, %1; cvt.u32.u64 %0, t; }" : "=r"(a) : "l"(p));
    return a;
}
__device__ __forceinline__ uint32_t sw128(uint32_t off) {
    return off ^ ((off >> 3) & 0x70);
}
__device__ __forceinline__ void ldsm_x4(uint32_t* r, uint32_t addr) {
    asm volatile("ldmatrix.sync.aligned.m8n8.x4.shared.b16 {%0,%1,%2,%3}, [%4];"
                 : "=r"(r[0]), "=r"(r[1]), "=r"(r[2]), "=r"(r[3]) : "r"(addr));
}
__device__ __forceinline__ void mma_bf16(float* c, const uint32_t* a, uint32_t b0, uint32_t b1) {
    asm volatile("mma.sync.aligned.m16n8k16.row.col.f32.bf16.bf16.f32 "
                 "{%0,%1,%2,%3}, {%4,%5,%6,%7}, {%8,%9}, {%0,%1,%2,%3};"
                 : "+f"(c[0]), "+f"(c[1]), "+f"(c[2]), "+f"(c[3])
                 : "r"(a[0]), "r"(a[1]), "r"(a[2]), "r"(a[3]), "r"(b0), "r"(b1));
}
__device__ __forceinline__ void cp16(uint32_t saddr, const void* gptr) {
    asm volatile("cp.async.cg.shared.global [%0], [%1], 16;"
                 :: "r"(saddr), "l"(__cvta_generic_to_global(gptr)));
}
#define CP_COMMIT() asm volatile("cp.async.commit_group;" ::: "memory")
#define CP_WAIT(n)  asm volatile("cp.async.wait_group %0;" :: "n"(n) : "memory")

// ---------------- kernel 1: rearrange + bf16 hi/lo split ----------------
__global__ void prep_kernel(const float* __restrict__ feats) {
    int q = blockIdx.x * 256 + threadIdx.x;
    int e = q * 4;
    int n = e >> 8;
    int d = e & 255;
    int v = n >> 11;
    int b = n & 2047;
    float4 f = *(const float4*)&feats[((b << 1) | v) * D_ + d];
    __nv_bfloat16 h0 = __float2bfloat16(f.x);
    __nv_bfloat16 h1 = __float2bfloat16(f.y);
    __nv_bfloat16 h2 = __float2bfloat16(f.z);
    __nv_bfloat16 h3 = __float2bfloat16(f.w);
    __nv_bfloat16 l0 = __float2bfloat16(f.x - __bfloat162float(h0));
    __nv_bfloat16 l1 = __float2bfloat16(f.y - __bfloat162float(h1));
    __nv_bfloat16 l2 = __float2bfloat16(f.z - __bfloat162float(h2));
    __nv_bfloat16 l3 = __float2bfloat16(f.w - __bfloat162float(h3));
    uint2 hp, lp;
    hp.x = ((uint32_t)__bfloat16_as_ushort(h1) << 16) | __bfloat16_as_ushort(h0);
    hp.y = ((uint32_t)__bfloat16_as_ushort(h3) << 16) | __bfloat16_as_ushort(h2);
    lp.x = ((uint32_t)__bfloat16_as_ushort(l1) << 16) | __bfloat16_as_ushort(l0);
    lp.y = ((uint32_t)__bfloat16_as_ushort(l3) << 16) | __bfloat16_as_ushort(l2);
    *(uint2*)&g_Fhi[e] = hp;
    *(uint2*)&g_Flo[e] = lp;
}

// ---------------- kernel 2: symmetric-tile GEMM, cp.async pipelined ----------------
#define OFF_AHI 0
#define OFF_ALO 16384
#define OFF_BHI 32768
#define OFF_BLO 49152
#define STAGE_BYTES 65536
#define SMEM_BYTES  (2 * STAGE_BYTES)

__global__ void __launch_bounds__(256) gemm_stats_kernel() {
    extern __shared__ char smem[];
    const uint32_t sb = smem_u32(smem);
    const int tid  = threadIdx.x;
    const int lane = tid & 31;
    const int wid  = tid >> 5;
    const int wm   = wid & 1;       // M half (64 rows)
    const int wn   = wid >> 1;      // N quarter (32 cols)

    // decode upper-triangular tile (bi, bj), bi <= bj
    int bi = 0, rem = blockIdx.x;
    while (rem >= (NB_ - bi)) { rem -= (NB_ - bi); bi++; }
    const int bj = bi + rem;
    const int row0 = bi * 128;
    const int col0 = bj * 128;

    // precompute the 4 staging coords for this thread
    int sr[4], sc[4];
    uint32_t ssw[4];
#pragma unroll
    for (int it = 0; it < 4; it++) {
        int q = tid + it * 256;
        sr[it] = q >> 3;
        sc[it] = q & 7;
        ssw[it] = sw128((uint32_t)(sr[it] * 128 + sc[it] * 16));
    }

    // prefetch chunk 0 into stage 0
    {
#pragma unroll
        for (int it = 0; it < 4; it++) {
            int srcA = (row0 + sr[it]) * D_ + sc[it] * 8;
            int srcB = (col0 + sr[it]) * D_ + sc[it] * 8;
            cp16(sb + OFF_AHI + ssw[it], &g_Fhi[srcA]);
            cp16(sb + OFF_ALO + ssw[it], &g_Flo[srcA]);
            cp16(sb + OFF_BHI + ssw[it], &g_Fhi[srcB]);
            cp16(sb + OFF_BLO + ssw[it], &g_Flo[srcB]);
        }
        CP_COMMIT();
    }

    float acc[4][4][4];
#pragma unroll
    for (int mi = 0; mi < 4; mi++)
#pragma unroll
        for (int nj = 0; nj < 4; nj++)
#pragma unroll
            for (int c = 0; c < 4; c++) acc[mi][nj][c] = 0.0f;

    const int arow  = wm * 64 + (lane & 7) + ((lane >> 3) & 1) * 8;
    const int akc0  = (lane >> 4) * 8;
    const int brow  = wn * 32 + (lane & 7) + (lane >> 4) * 8;
    const int bkc0  = ((lane >> 3) & 1) * 8;

    for (int kc = 0; kc < 4; kc++) {
        // prefetch next chunk into the other stage
        if (kc < 3) {
            uint32_t nb = sb + ((kc + 1) & 1) * STAGE_BYTES;
#pragma unroll
            for (int it = 0; it < 4; it++) {
                int srcA = (row0 + sr[it]) * D_ + (kc + 1) * 64 + sc[it] * 8;
                int srcB = (col0 + sr[it]) * D_ + (kc + 1) * 64 + sc[it] * 8;
                cp16(nb + OFF_AHI + ssw[it], &g_Fhi[srcA]);
                cp16(nb + OFF_ALO + ssw[it], &g_Flo[srcA]);
                cp16(nb + OFF_BHI + ssw[it], &g_Fhi[srcB]);
                cp16(nb + OFF_BLO + ssw[it], &g_Flo[srcB]);
            }
            CP_COMMIT();
            CP_WAIT(1);
        } else {
            CP_WAIT(0);
        }
        __syncthreads();

        const uint32_t cb = sb + (kc & 1) * STAGE_BYTES;
#pragma unroll
        for (int ks = 0; ks < 4; ks++) {
            const int akc = ks * 16 + akc0;
            const int bkc = ks * 16 + bkc0;
            uint32_t ahi[4][4], alo[4][4], bhi[2][4], blo[2][4];
            // hi x hi
#pragma unroll
            for (int mi = 0; mi < 4; mi++)
                ldsm_x4(ahi[mi], cb + OFF_AHI + sw128((uint32_t)((arow + mi * 16) * 128 + akc * 2)));
#pragma unroll
            for (int bi2 = 0; bi2 < 2; bi2++)
                ldsm_x4(bhi[bi2], cb + OFF_BHI + sw128((uint32_t)((brow + bi2 * 16) * 128 + bkc * 2)));
#pragma unroll
            for (int mi = 0; mi < 4; mi++)
#pragma unroll
                for (int nj = 0; nj < 4; nj++) {
                    uint32_t b0 = (nj & 1) ? bhi[nj >> 1][2] : bhi[nj >> 1][0];
                    uint32_t b1 = (nj & 1) ? bhi[nj >> 1][3] : bhi[nj >> 1][1];
                    mma_bf16(acc[mi][nj], ahi[mi], b0, b1);
                }
            // lo x hi (reuse bhi)
#pragma unroll
            for (int mi = 0; mi < 4; mi++)
                ldsm_x4(alo[mi], cb + OFF_ALO + sw128((uint32_t)((arow + mi * 16) * 128 + akc * 2)));
#pragma unroll
            for (int mi = 0; mi < 4; mi++)
#pragma unroll
                for (int nj = 0; nj < 4; nj++) {
                    uint32_t b0 = (nj & 1) ? bhi[nj >> 1][2] : bhi[nj >> 1][0];
                    uint32_t b1 = (nj & 1) ? bhi[nj >> 1][3] : bhi[nj >> 1][1];
                    mma_bf16(acc[mi][nj], alo[mi], b0, b1);
                }
            // hi x lo (reuse ahi)
#pragma unroll
            for (int bi2 = 0; bi2 < 2; bi2++)
                ldsm_x4(blo[bi2], cb + OFF_BLO + sw128((uint32_t)((brow + bi2 * 16) * 128 + bkc * 2)));
#pragma unroll
            for (int mi = 0; mi < 4; mi++)
#pragma unroll
                for (int nj = 0; nj < 4; nj++) {
                    uint32_t b0 = (nj & 1) ? blo[nj >> 1][2] : blo[nj >> 1][0];
                    uint32_t b1 = (nj & 1) ? blo[nj >> 1][3] : blo[nj >> 1][1];
                    mma_bf16(acc[mi][nj], ahi[mi], b0, b1);
                }
        }
        __syncthreads();   // all reads of this stage done before it is re-filled
    }

    // ---------------- epilogue ----------------
    float* redm = (float*)smem;          // [128][4] row partials
    float* reda = redm + 512;
    float* redw = reda + 512;
    float* colm = redw + 512;            // [128][2] col partials
    float* cola = colm + 256;
    float* colw = cola + 256;
    const float invT = 1.0f / TEMP_F;

    // --- row pass: rows of block bi over cols of block bj ---
#pragma unroll
    for (int mi = 0; mi < 4; mi++) {
#pragma unroll
        for (int h = 0; h < 2; h++) {
            int lr = wm * 64 + mi * 16 + h * 8 + (lane >> 2);
            int gi = row0 + lr;
            int posj = (gi + B_) & (NTOT - 1);
            float s[8];
#pragma unroll
            for (int nj = 0; nj < 4; nj++) {
                s[nj * 2]     = acc[mi][nj][h * 2]     * invT;
                s[nj * 2 + 1] = acc[mi][nj][h * 2 + 1] * invT;
            }
            float m = s[0];
#pragma unroll
            for (int i2 = 1; i2 < 8; i2++) m = fmaxf(m, s[i2]);
            m = fmaxf(m, __shfl_xor_sync(0xffffffffu, m, 1));
            m = fmaxf(m, __shfl_xor_sync(0xffffffffu, m, 2));
            float A = 0.0f, W = 0.0f;
#pragma unroll
            for (int nj = 0; nj < 4; nj++) {
#pragma unroll
                for (int c = 0; c < 2; c++) {
                    int gj = col0 + wn * 32 + nj * 8 + (lane & 3) * 2 + c;
                    float v = s[nj * 2 + c];
                    if (gj == posj) {
                        g_SP[gi] = v;
                    } else {
                        float e = __expf(v - m);
                        A += e;
                        W += e * (v - m);
                    }
                }
            }
            A += __shfl_xor_sync(0xffffffffu, A, 1);
            A += __shfl_xor_sync(0xffffffffu, A, 2);
            W += __shfl_xor_sync(0xffffffffu, W, 1);
            W += __shfl_xor_sync(0xffffffffu, W, 2);
            if ((lane & 3) == 0) {
                redm[lr * 4 + wn] = m;
                reda[lr * 4 + wn] = A;
                redw[lr * 4 + wn] = W;
            }
        }
    }

    // --- col pass (off-diagonal): rows of block bj over cols of block bi ---
    if (bi != bj) {
#pragma unroll
        for (int nj = 0; nj < 4; nj++) {
#pragma unroll
            for (int cbx = 0; cbx < 2; cbx++) {
                int cid = wn * 32 + nj * 8 + (lane & 3) * 2 + cbx;
                int gj = col0 + cid;
                int posi = (gj + B_) & (NTOT - 1);
                float sv[8];
#pragma unroll
                for (int mi = 0; mi < 4; mi++) {
                    sv[mi * 2]     = acc[mi][nj][cbx]     * invT;
                    sv[mi * 2 + 1] = acc[mi][nj][2 + cbx] * invT;
                }
                float m = sv[0];
#pragma unroll
                for (int i2 = 1; i2 < 8; i2++) m = fmaxf(m, sv[i2]);
                m = fmaxf(m, __shfl_xor_sync(0xffffffffu, m, 4));
                m = fmaxf(m, __shfl_xor_sync(0xffffffffu, m, 8));
                m = fmaxf(m, __shfl_xor_sync(0xffffffffu, m, 16));
                float A = 0.0f, W = 0.0f;
#pragma unroll
                for (int mi = 0; mi < 4; mi++) {
#pragma unroll
                    for (int h = 0; h < 2; h++) {
                        int gi = row0 + wm * 64 + mi * 16 + h * 8 + (lane >> 2);
                        float v = sv[mi * 2 + h];
                        if (gi == posi) {
                            g_SP[gj] = v;          // S symmetric
                        } else {
                            float e = __expf(v - m);
                            A += e;
                            W += e * (v - m);
                        }
                    }
                }
                A += __shfl_xor_sync(0xffffffffu, A, 4);
                A += __shfl_xor_sync(0xffffffffu, A, 8);
                A += __shfl_xor_sync(0xffffffffu, A, 16);
                W += __shfl_xor_sync(0xffffffffu, W, 4);
                W += __shfl_xor_sync(0xffffffffu, W, 8);
                W += __shfl_xor_sync(0xffffffffu, W, 16);
                if ((lane >> 2) == 0) {
                    colm[cid * 2 + wm] = m;
                    cola[cid * 2 + wm] = A;
                    colw[cid * 2 + wm] = W;
                }
            }
        }
    }

    __syncthreads();
    if (tid < 128) {
        float mm = redm[tid * 4], aa = reda[tid * 4], ww = redw[tid * 4];
#pragma unroll
        for (int t = 1; t < 4; t++) {
            float m2 = redm[tid * 4 + t];
            float a2 = reda[tid * 4 + t];
            float w2 = redw[tid * 4 + t];
            float mN = fmaxf(mm, m2);
            float c1 = __expf(mm - mN);
            float c2 = __expf(m2 - mN);
            ww = c1 * (ww + (mm - mN) * aa) + c2 * (w2 + (m2 - mN) * a2);
            aa = c1 * aa + c2 * a2;
            mm = mN;
        }
        g_Mp[bj * NTOT + row0 + tid] = mm;
        g_Ap[bj * NTOT + row0 + tid] = aa;
        g_Wp[bj * NTOT + row0 + tid] = ww;
    } else if (bi != bj && tid < 256) {
        int cid = tid - 128;
        float m1 = colm[cid * 2],     a1 = cola[cid * 2],     w1 = colw[cid * 2];
        float m2 = colm[cid * 2 + 1], a2 = cola[cid * 2 + 1], w2 = colw[cid * 2 + 1];
        float mN = fmaxf(m1, m2);
        float c1 = __expf(m1 - mN), c2 = __expf(m2 - mN);
        float ww = c1 * (w1 + (m1 - mN) * a1) + c2 * (w2 + (m2 - mN) * a2);
        float aa = c1 * a1 + c2 * a2;
        g_Mp[bi * NTOT + col0 + cid] = mN;
        g_Ap[bi * NTOT + col0 + cid] = aa;
        g_Wp[bi * NTOT + col0 + cid] = ww;
    }
}

// ---------------- kernel 3: fused combine + per-row loss partials ----------------
// Thread owns b in [0,2048); combines partials for rows b and b+2048, then both
// loss terms (they share u_new built from A[b] only).
__global__ void combine_loss_kernel(const int* __restrict__ index,
                                    const float* __restrict__ u) {
    __shared__ float red[8];
    int b = blockIdx.x * 256 + threadIdx.x;     // [0, 2048)
    float m1 = -1e30f, a1 = 0.0f, w1 = 0.0f;    // row b
    float m2 = -1e30f, a2 = 0.0f, w2 = 0.0f;    // row b+2048
#pragma unroll
    for (int s = 0; s < NB_; s++) {
        {
            float mx = g_Mp[s * NTOT + b];
            float ax = g_Ap[s * NTOT + b];
            float wx = g_Wp[s * NTOT + b];
            float mN = fmaxf(m1, mx);
            float c1 = __expf(m1 - mN);
            float c2 = __expf(mx - mN);
            w1 = c1 * (w1 + (m1 - mN) * a1) + c2 * (wx + (mx - mN) * ax);
            a1 = c1 * a1 + c2 * ax;
            m1 = mN;
        }
        {
            float mx = g_Mp[s * NTOT + B_ + b];
            float ax = g_Ap[s * NTOT + B_ + b];
            float wx = g_Wp[s * NTOT + B_ + b];
            float mN = fmaxf(m2, mx);
            float c1 = __expf(m2 - mN);
            float c2 = __expf(mx - mN);
            w2 = c1 * (w2 + (m2 - mN) * a2) + c2 * (wx + (mx - mN) * ax);
            a2 = c1 * a2 + c2 * ax;
            m2 = mN;
        }
    }
    float u_new = (1.0f - GAMMA_F) * u[index[b]] + GAMMA_F * a1;
    const float k = -(TEMP_F / BASET_F) * (1.0f / (float)NTOT);
    float val = k * (((g_SP[b] - m1) - w1 / u_new) +
                     ((g_SP[B_ + b] - m2) - w2 / u_new));
#pragma unroll
    for (int o = 16; o; o >>= 1) val += __shfl_down_sync(0xffffffffu, val, o);
    if ((threadIdx.x & 31) == 0) red[threadIdx.x >> 5] = val;
    __syncthreads();
    if (threadIdx.x < 8) {
        float v = red[threadIdx.x];
#pragma unroll
        for (int o = 4; o; o >>= 1) v += __shfl_down_sync(0xffu, v, o);
        if (threadIdx.x == 0) g_Lp[blockIdx.x] = v;
    }
}

__global__ void loss_final_kernel(float* __restrict__ out) {
    float v = (threadIdx.x < 8) ? g_Lp[threadIdx.x] : 0.0f;
#pragma unroll
    for (int o = 4; o; o >>= 1) v += __shfl_down_sync(0xffffffffu, v, o);
    if (threadIdx.x == 0) out[0] = v;
}

// ---------------- launch ----------------
extern "C" void kernel_launch(void* const* d_in, const int* in_sizes, int n_in,
                              void* d_out, int out_size) {
    const int*   d_index = nullptr;
    const float* d_feats = nullptr;
    const float* d_u     = nullptr;
    for (int i = 0; i < n_in; i++) {
        if (in_sizes[i] == B_)                 d_index = (const int*)d_in[i];
        else if (in_sizes[i] == B_ * V_ * D_)  d_feats = (const float*)d_in[i];
        else                                   d_u     = (const float*)d_in[i];
    }
    float* out = (float*)d_out;

    cudaFuncSetAttribute(gemm_stats_kernel,
                         cudaFuncAttributeMaxDynamicSharedMemorySize, SMEM_BYTES);

    prep_kernel<<<NTOT * D_ / 4 / 256, 256>>>(d_feats);
    gemm_stats_kernel<<<NTILES, 256, SMEM_BYTES>>>();
    combine_loss_kernel<<<B_ / 256, 256>>>(d_index, d_u);
    loss_final_kernel<<<1, 32>>>(out);
}

// round 7
// speedup vs baseline: 5.4583x; 1.4538x over previous
#include <cuda_runtime.h>
#include <cuda_fp16.h>
#include <stdint.h>

// ---------------- problem constants ----------------
#define B_    2048
#define V_    2
#define D_    256
#define NTOT  4096
#define NB_   32              // 128-wide blocks per dimension
#define NTILES 528            // NB*(NB+1)/2 upper-triangular tiles
#define GAMMA_F   0.9f
#define TEMP_F    0.07f
#define BASET_F   0.07f

// ---------------- device scratch ----------------
__device__ __half g_Fhi[NTOT * D_];
__device__ __half g_Flo[NTOT * D_];
__device__ float g_Mp[NB_ * NTOT];
__device__ float g_Ap[NB_ * NTOT];
__device__ float g_Wp[NB_ * NTOT];
__device__ float g_SP[NTOT];
__device__ float g_Lp[8];
__device__ unsigned int g_ctr;

// ---------------- helpers ----------------
__device__ __forceinline__ uint32_t smem_u32(const void* p) {
    uint32_t a;
    asm("{ .reg .u64 t; cvta.to.shared.u64 t, %1; cvt.u32.u64 %0, t; }" : "=r"(a) : "l"(p));
    return a;
}
__device__ __forceinline__ uint32_t sw128(uint32_t off) {
    return off ^ ((off >> 3) & 0x70);
}
__device__ __forceinline__ void ldsm_x4(uint32_t* r, uint32_t addr) {
    asm volatile("ldmatrix.sync.aligned.m8n8.x4.shared.b16 {%0,%1,%2,%3}, [%4];"
                 : "=r"(r[0]), "=r"(r[1]), "=r"(r[2]), "=r"(r[3]) : "r"(addr));
}
__device__ __forceinline__ void mma_f16(float* c, const uint32_t* a, uint32_t b0, uint32_t b1) {
    asm volatile("mma.sync.aligned.m16n8k16.row.col.f32.f16.f16.f32 "
                 "{%0,%1,%2,%3}, {%4,%5,%6,%7}, {%8,%9}, {%0,%1,%2,%3};"
                 : "+f"(c[0]), "+f"(c[1]), "+f"(c[2]), "+f"(c[3])
                 : "r"(a[0]), "r"(a[1]), "r"(a[2]), "r"(a[3]), "r"(b0), "r"(b1));
}
__device__ __forceinline__ void cp16(uint32_t saddr, const void* gptr) {
    asm volatile("cp.async.cg.shared.global [%0], [%1], 16;"
                 :: "r"(saddr), "l"(__cvta_generic_to_global(gptr)));
}
#define CP_COMMIT() asm volatile("cp.async.commit_group;" ::: "memory")
#define CP_WAIT(n)  asm volatile("cp.async.wait_group %0;" :: "n"(n) : "memory")

// ---------------- kernel 1: rearrange + fp16 hi/lo split ----------------
__global__ void prep_kernel(const float* __restrict__ feats) {
    if (blockIdx.x == 0 && threadIdx.x == 0) g_ctr = 0;   // reset ticket each replay
    int q = blockIdx.x * 256 + threadIdx.x;
    int e = q * 4;
    int n = e >> 8;
    int d = e & 255;
    int v = n >> 11;
    int b = n & 2047;
    float4 f = *(const float4*)&feats[((b << 1) | v) * D_ + d];
    __half h0 = __float2half(f.x);
    __half h1 = __float2half(f.y);
    __half h2 = __float2half(f.z);
    __half h3 = __float2half(f.w);
    __half l0 = __float2half(f.x - __half2float(h0));
    __half l1 = __float2half(f.y - __half2float(h1));
    __half l2 = __float2half(f.z - __half2float(h2));
    __half l3 = __float2half(f.w - __half2float(h3));
    uint2 hp, lp;
    hp.x = ((uint32_t)__half_as_ushort(h1) << 16) | __half_as_ushort(h0);
    hp.y = ((uint32_t)__half_as_ushort(h3) << 16) | __half_as_ushort(h2);
    lp.x = ((uint32_t)__half_as_ushort(l1) << 16) | __half_as_ushort(l0);
    lp.y = ((uint32_t)__half_as_ushort(l3) << 16) | __half_as_ushort(l2);
    *(uint2*)&g_Fhi[e] = hp;
    *(uint2*)&g_Flo[e] = lp;
}

// ---------------- kernel 2: symmetric-tile GEMM (2-pass fp16), cp.async ----------------
// S[i,j] ~= hi_i.hi_j + hi_i.lo_j   (lo_i.hi_j dropped: ~2e-4 per logit)
#define OFF_AHI 0
#define OFF_BHI 16384
#define OFF_BLO 32768
#define STAGE_BYTES 49152
#define SMEM_BYTES  (2 * STAGE_BYTES)

__global__ void __launch_bounds__(256, 2) gemm_stats_kernel() {
    extern __shared__ char smem[];
    const uint32_t sb = smem_u32(smem);
    const int tid  = threadIdx.x;
    const int lane = tid & 31;
    const int wid  = tid >> 5;
    const int wm   = wid & 1;       // M half (64 rows)
    const int wn   = wid >> 1;      // N quarter (32 cols)

    // decode upper-triangular tile (bi, bj), bi <= bj
    int bi = 0, rem = blockIdx.x;
    while (rem >= (NB_ - bi)) { rem -= (NB_ - bi); bi++; }
    const int bj = bi + rem;
    const int row0 = bi * 128;
    const int col0 = bj * 128;

    // staging coords (1024 16B-chunks per 16KB array / 256 threads = 4 each)
    int sr[4], sc[4];
    uint32_t ssw[4];
#pragma unroll
    for (int it = 0; it < 4; it++) {
        int q = tid + it * 256;
        sr[it] = q >> 3;
        sc[it] = q & 7;
        ssw[it] = sw128((uint32_t)(sr[it] * 128 + sc[it] * 16));
    }

    // prefetch chunk 0 into stage 0
#pragma unroll
    for (int it = 0; it < 4; it++) {
        int srcA = (row0 + sr[it]) * D_ + sc[it] * 8;
        int srcB = (col0 + sr[it]) * D_ + sc[it] * 8;
        cp16(sb + OFF_AHI + ssw[it], &g_Fhi[srcA]);
        cp16(sb + OFF_BHI + ssw[it], &g_Fhi[srcB]);
        cp16(sb + OFF_BLO + ssw[it], &g_Flo[srcB]);
    }
    CP_COMMIT();

    float acc[4][4][4];
#pragma unroll
    for (int mi = 0; mi < 4; mi++)
#pragma unroll
        for (int nj = 0; nj < 4; nj++)
#pragma unroll
            for (int c = 0; c < 4; c++) acc[mi][nj][c] = 0.0f;

    const int arow  = wm * 64 + (lane & 7) + ((lane >> 3) & 1) * 8;
    const int akc0  = (lane >> 4) * 8;
    const int brow  = wn * 32 + (lane & 7) + (lane >> 4) * 8;
    const int bkc0  = ((lane >> 3) & 1) * 8;

    for (int kc = 0; kc < 4; kc++) {
        if (kc < 3) {
            uint32_t nb = sb + ((kc + 1) & 1) * STAGE_BYTES;
#pragma unroll
            for (int it = 0; it < 4; it++) {
                int srcA = (row0 + sr[it]) * D_ + (kc + 1) * 64 + sc[it] * 8;
                int srcB = (col0 + sr[it]) * D_ + (kc + 1) * 64 + sc[it] * 8;
                cp16(nb + OFF_AHI + ssw[it], &g_Fhi[srcA]);
                cp16(nb + OFF_BHI + ssw[it], &g_Fhi[srcB]);
                cp16(nb + OFF_BLO + ssw[it], &g_Flo[srcB]);
            }
            CP_COMMIT();
            CP_WAIT(1);
        } else {
            CP_WAIT(0);
        }
        __syncthreads();

        const uint32_t cb = sb + (kc & 1) * STAGE_BYTES;
#pragma unroll
        for (int ks = 0; ks < 4; ks++) {
            const int akc = ks * 16 + akc0;
            const int bkc = ks * 16 + bkc0;
            uint32_t ahi[4][4], bhi[2][4], blo[2][4];
#pragma unroll
            for (int mi = 0; mi < 4; mi++)
                ldsm_x4(ahi[mi], cb + OFF_AHI + sw128((uint32_t)((arow + mi * 16) * 128 + akc * 2)));
#pragma unroll
            for (int b2 = 0; b2 < 2; b2++)
                ldsm_x4(bhi[b2], cb + OFF_BHI + sw128((uint32_t)((brow + b2 * 16) * 128 + bkc * 2)));
            // hi x hi
#pragma unroll
            for (int mi = 0; mi < 4; mi++)
#pragma unroll
                for (int nj = 0; nj < 4; nj++) {
                    uint32_t b0 = (nj & 1) ? bhi[nj >> 1][2] : bhi[nj >> 1][0];
                    uint32_t b1 = (nj & 1) ? bhi[nj >> 1][3] : bhi[nj >> 1][1];
                    mma_f16(acc[mi][nj], ahi[mi], b0, b1);
                }
            // hi x lo (reuse ahi)
#pragma unroll
            for (int b2 = 0; b2 < 2; b2++)
                ldsm_x4(blo[b2], cb + OFF_BLO + sw128((uint32_t)((brow + b2 * 16) * 128 + bkc * 2)));
#pragma unroll
            for (int mi = 0; mi < 4; mi++)
#pragma unroll
                for (int nj = 0; nj < 4; nj++) {
                    uint32_t b0 = (nj & 1) ? blo[nj >> 1][2] : blo[nj >> 1][0];
                    uint32_t b1 = (nj & 1) ? blo[nj >> 1][3] : blo[nj >> 1][1];
                    mma_f16(acc[mi][nj], ahi[mi], b0, b1);
                }
        }
        __syncthreads();
    }

    // ---------------- epilogue ----------------
    float* redm = (float*)smem;          // [128][4] row partials
    float* reda = redm + 512;
    float* redw = reda + 512;
    float* colm = redw + 512;            // [128][2] col partials
    float* cola = colm + 256;
    float* colw = cola + 256;
    const float invT = 1.0f / TEMP_F;

    // --- row pass: rows of block bi over cols of block bj ---
#pragma unroll
    for (int mi = 0; mi < 4; mi++) {
#pragma unroll
        for (int h = 0; h < 2; h++) {
            int lr = wm * 64 + mi * 16 + h * 8 + (lane >> 2);
            int gi = row0 + lr;
            int posj = (gi + B_) & (NTOT - 1);
            float s[8];
#pragma unroll
            for (int nj = 0; nj < 4; nj++) {
                s[nj * 2]     = acc[mi][nj][h * 2]     * invT;
                s[nj * 2 + 1] = acc[mi][nj][h * 2 + 1] * invT;
            }
            float m = s[0];
#pragma unroll
            for (int i2 = 1; i2 < 8; i2++) m = fmaxf(m, s[i2]);
            m = fmaxf(m, __shfl_xor_sync(0xffffffffu, m, 1));
            m = fmaxf(m, __shfl_xor_sync(0xffffffffu, m, 2));
            float A = 0.0f, W = 0.0f;
#pragma unroll
            for (int nj = 0; nj < 4; nj++) {
#pragma unroll
                for (int c = 0; c < 2; c++) {
                    int gj = col0 + wn * 32 + nj * 8 + (lane & 3) * 2 + c;
                    float v = s[nj * 2 + c];
                    if (gj == posj) {
                        g_SP[gi] = v;
                    } else {
                        float e = __expf(v - m);
                        A += e;
                        W += e * (v - m);
                    }
                }
            }
            A += __shfl_xor_sync(0xffffffffu, A, 1);
            A += __shfl_xor_sync(0xffffffffu, A, 2);
            W += __shfl_xor_sync(0xffffffffu, W, 1);
            W += __shfl_xor_sync(0xffffffffu, W, 2);
            if ((lane & 3) == 0) {
                redm[lr * 4 + wn] = m;
                reda[lr * 4 + wn] = A;
                redw[lr * 4 + wn] = W;
            }
        }
    }

    // --- col pass (off-diagonal): rows of block bj over cols of block bi ---
    if (bi != bj) {
#pragma unroll
        for (int nj = 0; nj < 4; nj++) {
#pragma unroll
            for (int cbx = 0; cbx < 2; cbx++) {
                int cid = wn * 32 + nj * 8 + (lane & 3) * 2 + cbx;
                int gj = col0 + cid;
                int posi = (gj + B_) & (NTOT - 1);
                float sv[8];
#pragma unroll
                for (int mi = 0; mi < 4; mi++) {
                    sv[mi * 2]     = acc[mi][nj][cbx]     * invT;
                    sv[mi * 2 + 1] = acc[mi][nj][2 + cbx] * invT;
                }
                float m = sv[0];
#pragma unroll
                for (int i2 = 1; i2 < 8; i2++) m = fmaxf(m, sv[i2]);
                m = fmaxf(m, __shfl_xor_sync(0xffffffffu, m, 4));
                m = fmaxf(m, __shfl_xor_sync(0xffffffffu, m, 8));
                m = fmaxf(m, __shfl_xor_sync(0xffffffffu, m, 16));
                float A = 0.0f, W = 0.0f;
#pragma unroll
                for (int mi = 0; mi < 4; mi++) {
#pragma unroll
                    for (int h = 0; h < 2; h++) {
                        int gi = row0 + wm * 64 + mi * 16 + h * 8 + (lane >> 2);
                        float v = sv[mi * 2 + h];
                        if (gi == posi) {
                            g_SP[gj] = v;          // S symmetric
                        } else {
                            float e = __expf(v - m);
                            A += e;
                            W += e * (v - m);
                        }
                    }
                }
                A += __shfl_xor_sync(0xffffffffu, A, 4);
                A += __shfl_xor_sync(0xffffffffu, A, 8);
                A += __shfl_xor_sync(0xffffffffu, A, 16);
                W += __shfl_xor_sync(0xffffffffu, W, 4);
                W += __shfl_xor_sync(0xffffffffu, W, 8);
                W += __shfl_xor_sync(0xffffffffu, W, 16);
                if ((lane >> 2) == 0) {
                    colm[cid * 2 + wm] = m;
                    cola[cid * 2 + wm] = A;
                    colw[cid * 2 + wm] = W;
                }
            }
        }
    }

    __syncthreads();
    if (tid < 128) {
        float mm = redm[tid * 4], aa = reda[tid * 4], ww = redw[tid * 4];
#pragma unroll
        for (int t = 1; t < 4; t++) {
            float m2 = redm[tid * 4 + t];
            float a2 = reda[tid * 4 + t];
            float w2 = redw[tid * 4 + t];
            float mN = fmaxf(mm, m2);
            float c1 = __expf(mm - mN);
            float c2 = __expf(m2 - mN);
            ww = c1 * (ww + (mm - mN) * aa) + c2 * (w2 + (m2 - mN) * a2);
            aa = c1 * aa + c2 * a2;
            mm = mN;
        }
        g_Mp[bj * NTOT + row0 + tid] = mm;
        g_Ap[bj * NTOT + row0 + tid] = aa;
        g_Wp[bj * NTOT + row0 + tid] = ww;
    } else if (bi != bj && tid < 256) {
        int cid = tid - 128;
        float m1 = colm[cid * 2],     a1 = cola[cid * 2],     w1 = colw[cid * 2];
        float m2 = colm[cid * 2 + 1], a2 = cola[cid * 2 + 1], w2 = colw[cid * 2 + 1];
        float mN = fmaxf(m1, m2);
        float c1 = __expf(m1 - mN), c2 = __expf(m2 - mN);
        float ww = c1 * (w1 + (m1 - mN) * a1) + c2 * (w2 + (m2 - mN) * a2);
        float aa = c1 * a1 + c2 * a2;
        g_Mp[bi * NTOT + col0 + cid] = mN;
        g_Ap[bi * NTOT + col0 + cid] = aa;
        g_Wp[bi * NTOT + col0 + cid] = ww;
    }
}

// ---------------- kernel 3: combine + loss + last-block final reduce ----------------
__global__ void combine_loss_kernel(const int* __restrict__ index,
                                    const float* __restrict__ u,
                                    float* __restrict__ out) {
    __shared__ float red[8];
    int b = blockIdx.x * 256 + threadIdx.x;     // [0, 2048)
    float m1 = -1e30f, a1 = 0.0f, w1 = 0.0f;    // row b
    float m2 = -1e30f, a2 = 0.0f, w2 = 0.0f;    // row b+2048
#pragma unroll
    for (int s = 0; s < NB_; s++) {
        {
            float mx = g_Mp[s * NTOT + b];
            float ax = g_Ap[s * NTOT + b];
            float wx = g_Wp[s * NTOT + b];
            float mN = fmaxf(m1, mx);
            float c1 = __expf(m1 - mN);
            float c2 = __expf(mx - mN);
            w1 = c1 * (w1 + (m1 - mN) * a1) + c2 * (wx + (mx - mN) * ax);
            a1 = c1 * a1 + c2 * ax;
            m1 = mN;
        }
        {
            float mx = g_Mp[s * NTOT + B_ + b];
            float ax = g_Ap[s * NTOT + B_ + b];
            float wx = g_Wp[s * NTOT + B_ + b];
            float mN = fmaxf(m2, mx);
            float c1 = __expf(m2 - mN);
            float c2 = __expf(mx - mN);
            w2 = c1 * (w2 + (m2 - mN) * a2) + c2 * (wx + (mx - mN) * ax);
            a2 = c1 * a2 + c2 * ax;
            m2 = mN;
        }
    }
    float u_new = (1.0f - GAMMA_F) * u[index[b]] + GAMMA_F * a1;
    const float k = -(TEMP_F / BASET_F) * (1.0f / (float)NTOT);
    float val = k * (((g_SP[b] - m1) - w1 / u_new) +
                     ((g_SP[B_ + b] - m2) - w2 / u_new));
#pragma unroll
    for (int o = 16; o; o >>= 1) val += __shfl_down_sync(0xffffffffu, val, o);
    if ((threadIdx.x & 31) == 0) red[threadIdx.x >> 5] = val;
    __syncthreads();
    if (threadIdx.x < 8) {
        float v = red[threadIdx.x];
#pragma unroll
        for (int o = 4; o; o >>= 1) v += __shfl_down_sync(0xffu, v, o);
        if (threadIdx.x == 0) {
            g_Lp[blockIdx.x] = v;
            __threadfence();
            unsigned int t = atomicAdd(&g_ctr, 1u);
            if (t == gridDim.x - 1) {            // last block: fixed-order final sum
                float s = 0.0f;
#pragma unroll
                for (int i = 0; i < 8; i++) s += g_Lp[i];
                out[0] = s;
            }
        }
    }
}

// ---------------- launch ----------------
extern "C" void kernel_launch(void* const* d_in, const int* in_sizes, int n_in,
                              void* d_out, int out_size) {
    const int*   d_index = nullptr;
    const float* d_feats = nullptr;
    const float* d_u     = nullptr;
    for (int i = 0; i < n_in; i++) {
        if (in_sizes[i] == B_)                 d_index = (const int*)d_in[i];
        else if (in_sizes[i] == B_ * V_ * D_)  d_feats = (const float*)d_in[i];
        else                                   d_u     = (const float*)d_in[i];
    }
    float* out = (float*)d_out;

    cudaFuncSetAttribute(gemm_stats_kernel,
                         cudaFuncAttributeMaxDynamicSharedMemorySize, SMEM_BYTES);

    prep_kernel<<<NTOT * D_ / 4 / 256, 256>>>(d_feats);
    gemm_stats_kernel<<<NTILES, 256, SMEM_BYTES>>>();
    combine_loss_kernel<<<B_ / 256, 256>>>(d_index, d_u, out);
}

// round 8
// speedup vs baseline: 6.9115x; 1.2662x over previous
#include <cuda_runtime.h>
#include <cuda_fp16.h>
#include <stdint.h>

// ---------------- problem constants ----------------
#define B_    2048
#define V_    2
#define D_    256
#define NTOT  4096
#define NB_   32              // 128-wide blocks per dimension
#define NTILES 528            // NB*(NB+1)/2 upper-triangular tiles
#define GAMMA_F   0.9f
#define TEMP_F    0.07f
#define BASET_F   0.07f

// ---------------- device scratch ----------------
__device__ __half g_Fh[NTOT * D_];
__device__ float g_Mp[NB_ * NTOT];
__device__ float g_Ap[NB_ * NTOT];
__device__ float g_Wp[NB_ * NTOT];
__device__ float g_SP[NTOT];
__device__ float g_Lp[8];
__device__ unsigned int g_ctr;

// ---------------- helpers ----------------
__device__ __forceinline__ uint32_t smem_u32(const void* p) {
    uint32_t a;
    asm("{ .reg .u64 t; cvta.to.shared.u64 t, %1; cvt.u32.u64 %0, t; }" : "=r"(a) : "l"(p));
    return a;
}
__device__ __forceinline__ uint32_t sw128(uint32_t off) {
    return off ^ ((off >> 3) & 0x70);
}
__device__ __forceinline__ void ldsm_x4(uint32_t* r, uint32_t addr) {
    asm volatile("ldmatrix.sync.aligned.m8n8.x4.shared.b16 {%0,%1,%2,%3}, [%4];"
                 : "=r"(r[0]), "=r"(r[1]), "=r"(r[2]), "=r"(r[3]) : "r"(addr));
}
__device__ __forceinline__ void mma_f16(float* c, const uint32_t* a, uint32_t b0, uint32_t b1) {
    asm volatile("mma.sync.aligned.m16n8k16.row.col.f32.f16.f16.f32 "
                 "{%0,%1,%2,%3}, {%4,%5,%6,%7}, {%8,%9}, {%0,%1,%2,%3};"
                 : "+f"(c[0]), "+f"(c[1]), "+f"(c[2]), "+f"(c[3])
                 : "r"(a[0]), "r"(a[1]), "r"(a[2]), "r"(a[3]), "r"(b0), "r"(b1));
}
__device__ __forceinline__ void cp16(uint32_t saddr, const void* gptr) {
    asm volatile("cp.async.cg.shared.global [%0], [%1], 16;"
                 :: "r"(saddr), "l"(__cvta_generic_to_global(gptr)));
}
#define CP_COMMIT() asm volatile("cp.async.commit_group;" ::: "memory")
#define CP_WAIT(n)  asm volatile("cp.async.wait_group %0;" :: "n"(n) : "memory")

// ---------------- kernel 1: rearrange -> fp16 ----------------
__global__ void prep_kernel(const float* __restrict__ feats) {
    if (blockIdx.x == 0 && threadIdx.x == 0) g_ctr = 0;   // reset ticket each replay
    int q = blockIdx.x * 256 + threadIdx.x;
    int e = q * 4;
    int n = e >> 8;
    int d = e & 255;
    int v = n >> 11;
    int b = n & 2047;
    float4 f = *(const float4*)&feats[((b << 1) | v) * D_ + d];
    uint2 hp;
    hp.x = ((uint32_t)__half_as_ushort(__float2half(f.y)) << 16) | __half_as_ushort(__float2half(f.x));
    hp.y = ((uint32_t)__half_as_ushort(__float2half(f.w)) << 16) | __half_as_ushort(__float2half(f.z));
    *(uint2*)&g_Fh[e] = hp;
}

// ---------------- kernel 2: symmetric-tile fp16 GEMM + fused stats ----------------
#define OFF_A 0
#define OFF_B 16384
#define STAGE_BYTES 32768
#define SMEM_BYTES  (2 * STAGE_BYTES)

__global__ void __launch_bounds__(256, 2) gemm_stats_kernel() {
    extern __shared__ char smem[];
    const uint32_t sb = smem_u32(smem);
    const int tid  = threadIdx.x;
    const int lane = tid & 31;
    const int wid  = tid >> 5;
    const int wm   = wid & 1;       // M half (64 rows)
    const int wn   = wid >> 1;      // N quarter (32 cols)

    // decode upper-triangular tile (bi, bj), bi <= bj
    int bi = 0, rem = blockIdx.x;
    while (rem >= (NB_ - bi)) { rem -= (NB_ - bi); bi++; }
    const int bj = bi + rem;
    const int row0 = bi * 128;
    const int col0 = bj * 128;

    // staging coords
    int sr[4], sc[4];
    uint32_t ssw[4];
#pragma unroll
    for (int it = 0; it < 4; it++) {
        int q = tid + it * 256;
        sr[it] = q >> 3;
        sc[it] = q & 7;
        ssw[it] = sw128((uint32_t)(sr[it] * 128 + sc[it] * 16));
    }

    // prefetch chunk 0 into stage 0
#pragma unroll
    for (int it = 0; it < 4; it++) {
        cp16(sb + OFF_A + ssw[it], &g_Fh[(row0 + sr[it]) * D_ + sc[it] * 8]);
        cp16(sb + OFF_B + ssw[it], &g_Fh[(col0 + sr[it]) * D_ + sc[it] * 8]);
    }
    CP_COMMIT();

    float acc[4][4][4];
#pragma unroll
    for (int mi = 0; mi < 4; mi++)
#pragma unroll
        for (int nj = 0; nj < 4; nj++)
#pragma unroll
            for (int c = 0; c < 4; c++) acc[mi][nj][c] = 0.0f;

    const int arow  = wm * 64 + (lane & 7) + ((lane >> 3) & 1) * 8;
    const int akc0  = (lane >> 4) * 8;
    const int brow  = wn * 32 + (lane & 7) + (lane >> 4) * 8;
    const int bkc0  = ((lane >> 3) & 1) * 8;

    for (int kc = 0; kc < 4; kc++) {
        if (kc < 3) {
            uint32_t nb = sb + ((kc + 1) & 1) * STAGE_BYTES;
#pragma unroll
            for (int it = 0; it < 4; it++) {
                cp16(nb + OFF_A + ssw[it], &g_Fh[(row0 + sr[it]) * D_ + (kc + 1) * 64 + sc[it] * 8]);
                cp16(nb + OFF_B + ssw[it], &g_Fh[(col0 + sr[it]) * D_ + (kc + 1) * 64 + sc[it] * 8]);
            }
            CP_COMMIT();
            CP_WAIT(1);
        } else {
            CP_WAIT(0);
        }
        __syncthreads();

        const uint32_t cb = sb + (kc & 1) * STAGE_BYTES;
#pragma unroll
        for (int ks = 0; ks < 4; ks++) {
            const int akc = ks * 16 + akc0;
            const int bkc = ks * 16 + bkc0;
            uint32_t a[4][4], b[2][4];
#pragma unroll
            for (int mi = 0; mi < 4; mi++)
                ldsm_x4(a[mi], cb + OFF_A + sw128((uint32_t)((arow + mi * 16) * 128 + akc * 2)));
#pragma unroll
            for (int b2 = 0; b2 < 2; b2++)
                ldsm_x4(b[b2], cb + OFF_B + sw128((uint32_t)((brow + b2 * 16) * 128 + bkc * 2)));
#pragma unroll
            for (int mi = 0; mi < 4; mi++)
#pragma unroll
                for (int nj = 0; nj < 4; nj++) {
                    uint32_t b0 = (nj & 1) ? b[nj >> 1][2] : b[nj >> 1][0];
                    uint32_t b1 = (nj & 1) ? b[nj >> 1][3] : b[nj >> 1][1];
                    mma_f16(acc[mi][nj], a[mi], b0, b1);
                }
        }
        __syncthreads();
    }

    // ---------------- epilogue ----------------
    float* redm = (float*)smem;          // [128][4] row partials
    float* reda = redm + 512;
    float* redw = reda + 512;
    float* colm = redw + 512;            // [128][2] col partials
    float* cola = colm + 256;
    float* colw = cola + 256;
    const float invT = 1.0f / TEMP_F;

    // --- row pass: rows of block bi over cols of block bj ---
#pragma unroll
    for (int mi = 0; mi < 4; mi++) {
#pragma unroll
        for (int h = 0; h < 2; h++) {
            int lr = wm * 64 + mi * 16 + h * 8 + (lane >> 2);
            int gi = row0 + lr;
            int posj = (gi + B_) & (NTOT - 1);
            float s[8];
#pragma unroll
            for (int nj = 0; nj < 4; nj++) {
                s[nj * 2]     = acc[mi][nj][h * 2]     * invT;
                s[nj * 2 + 1] = acc[mi][nj][h * 2 + 1] * invT;
            }
            float m = s[0];
#pragma unroll
            for (int i2 = 1; i2 < 8; i2++) m = fmaxf(m, s[i2]);
            m = fmaxf(m, __shfl_xor_sync(0xffffffffu, m, 1));
            m = fmaxf(m, __shfl_xor_sync(0xffffffffu, m, 2));
            float A = 0.0f, W = 0.0f;
#pragma unroll
            for (int nj = 0; nj < 4; nj++) {
#pragma unroll
                for (int c = 0; c < 2; c++) {
                    int gj = col0 + wn * 32 + nj * 8 + (lane & 3) * 2 + c;
                    float v = s[nj * 2 + c];
                    if (gj == posj) {
                        g_SP[gi] = v;
                    } else {
                        float e = __expf(v - m);
                        A += e;
                        W += e * (v - m);
                    }
                }
            }
            A += __shfl_xor_sync(0xffffffffu, A, 1);
            A += __shfl_xor_sync(0xffffffffu, A, 2);
            W += __shfl_xor_sync(0xffffffffu, W, 1);
            W += __shfl_xor_sync(0xffffffffu, W, 2);
            if ((lane & 3) == 0) {
                redm[lr * 4 + wn] = m;
                reda[lr * 4 + wn] = A;
                redw[lr * 4 + wn] = W;
            }
        }
    }

    // --- col pass (off-diagonal): rows of block bj over cols of block bi ---
    if (bi != bj) {
#pragma unroll
        for (int nj = 0; nj < 4; nj++) {
#pragma unroll
            for (int cbx = 0; cbx < 2; cbx++) {
                int cid = wn * 32 + nj * 8 + (lane & 3) * 2 + cbx;
                int gj = col0 + cid;
                int posi = (gj + B_) & (NTOT - 1);
                float sv[8];
#pragma unroll
                for (int mi = 0; mi < 4; mi++) {
                    sv[mi * 2]     = acc[mi][nj][cbx]     * invT;
                    sv[mi * 2 + 1] = acc[mi][nj][2 + cbx] * invT;
                }
                float m = sv[0];
#pragma unroll
                for (int i2 = 1; i2 < 8; i2++) m = fmaxf(m, sv[i2]);
                m = fmaxf(m, __shfl_xor_sync(0xffffffffu, m, 4));
                m = fmaxf(m, __shfl_xor_sync(0xffffffffu, m, 8));
                m = fmaxf(m, __shfl_xor_sync(0xffffffffu, m, 16));
                float A = 0.0f, W = 0.0f;
#pragma unroll
                for (int mi = 0; mi < 4; mi++) {
#pragma unroll
                    for (int h = 0; h < 2; h++) {
                        int gi = row0 + wm * 64 + mi * 16 + h * 8 + (lane >> 2);
                        float v = sv[mi * 2 + h];
                        if (gi == posi) {
                            g_SP[gj] = v;          // S symmetric
                        } else {
                            float e = __expf(v - m);
                            A += e;
                            W += e * (v - m);
                        }
                    }
                }
                A += __shfl_xor_sync(0xffffffffu, A, 4);
                A += __shfl_xor_sync(0xffffffffu, A, 8);
                A += __shfl_xor_sync(0xffffffffu, A, 16);
                W += __shfl_xor_sync(0xffffffffu, W, 4);
                W += __shfl_xor_sync(0xffffffffu, W, 8);
                W += __shfl_xor_sync(0xffffffffu, W, 16);
                if ((lane >> 2) == 0) {
                    colm[cid * 2 + wm] = m;
                    cola[cid * 2 + wm] = A;
                    colw[cid * 2 + wm] = W;
                }
            }
        }
    }

    __syncthreads();
    if (tid < 128) {
        float mm = redm[tid * 4], aa = reda[tid * 4], ww = redw[tid * 4];
#pragma unroll
        for (int t = 1; t < 4; t++) {
            float m2 = redm[tid * 4 + t];
            float a2 = reda[tid * 4 + t];
            float w2 = redw[tid * 4 + t];
            float mN = fmaxf(mm, m2);
            float c1 = __expf(mm - mN);
            float c2 = __expf(m2 - mN);
            ww = c1 * (ww + (mm - mN) * aa) + c2 * (w2 + (m2 - mN) * a2);
            aa = c1 * aa + c2 * a2;
            mm = mN;
        }
        g_Mp[bj * NTOT + row0 + tid] = mm;
        g_Ap[bj * NTOT + row0 + tid] = aa;
        g_Wp[bj * NTOT + row0 + tid] = ww;
    } else if (bi != bj && tid < 256) {
        int cid = tid - 128;
        float m1 = colm[cid * 2],     a1 = cola[cid * 2],     w1 = colw[cid * 2];
        float m2 = colm[cid * 2 + 1], a2 = cola[cid * 2 + 1], w2 = colw[cid * 2 + 1];
        float mN = fmaxf(m1, m2);
        float c1 = __expf(m1 - mN), c2 = __expf(m2 - mN);
        float ww = c1 * (w1 + (m1 - mN) * a1) + c2 * (w2 + (m2 - mN) * a2);
        float aa = c1 * a1 + c2 * a2;
        g_Mp[bi * NTOT + col0 + cid] = mN;
        g_Ap[bi * NTOT + col0 + cid] = aa;
        g_Wp[bi * NTOT + col0 + cid] = ww;
    }
}

// ---------------- kernel 3: combine + loss + last-block final reduce ----------------
__global__ void combine_loss_kernel(const int* __restrict__ index,
                                    const float* __restrict__ u,
                                    float* __restrict__ out) {
    __shared__ float red[8];
    int b = blockIdx.x * 256 + threadIdx.x;     // [0, 2048)
    float m1 = -1e30f, a1 = 0.0f, w1 = 0.0f;    // row b
    float m2 = -1e30f, a2 = 0.0f, w2 = 0.0f;    // row b+2048
#pragma unroll
    for (int s = 0; s < NB_; s++) {
        {
            float mx = g_Mp[s * NTOT + b];
            float ax = g_Ap[s * NTOT + b];
            float wx = g_Wp[s * NTOT + b];
            float mN = fmaxf(m1, mx);
            float c1 = __expf(m1 - mN);
            float c2 = __expf(mx - mN);
            w1 = c1 * (w1 + (m1 - mN) * a1) + c2 * (wx + (mx - mN) * ax);
            a1 = c1 * a1 + c2 * ax;
            m1 = mN;
        }
        {
            float mx = g_Mp[s * NTOT + B_ + b];
            float ax = g_Ap[s * NTOT + B_ + b];
            float wx = g_Wp[s * NTOT + B_ + b];
            float mN = fmaxf(m2, mx);
            float c1 = __expf(m2 - mN);
            float c2 = __expf(mx - mN);
            w2 = c1 * (w2 + (m2 - mN) * a2) + c2 * (wx + (mx - mN) * ax);
            a2 = c1 * a2 + c2 * ax;
            m2 = mN;
        }
    }
    float u_new = (1.0f - GAMMA_F) * u[index[b]] + GAMMA_F * a1;
    const float k = -(TEMP_F / BASET_F) * (1.0f / (float)NTOT);
    float val = k * (((g_SP[b] - m1) - w1 / u_new) +
                     ((g_SP[B_ + b] - m2) - w2 / u_new));
#pragma unroll
    for (int o = 16; o; o >>= 1) val += __shfl_down_sync(0xffffffffu, val, o);
    if ((threadIdx.x & 31) == 0) red[threadIdx.x >> 5] = val;
    __syncthreads();
    if (threadIdx.x < 8) {
        float v = red[threadIdx.x];
#pragma unroll
        for (int o = 4; o; o >>= 1) v += __shfl_down_sync(0xffu, v, o);
        if (threadIdx.x == 0) {
            g_Lp[blockIdx.x] = v;
            __threadfence();
            unsigned int t = atomicAdd(&g_ctr, 1u);
            if (t == gridDim.x - 1) {            // last block: fixed-order final sum
                float s = 0.0f;
#pragma unroll
                for (int i = 0; i < 8; i++) s += g_Lp[i];
                out[0] = s;
            }
        }
    }
}

// ---------------- launch ----------------
extern "C" void kernel_launch(void* const* d_in, const int* in_sizes, int n_in,
                              void* d_out, int out_size) {
    const int*   d_index = nullptr;
    const float* d_feats = nullptr;
    const float* d_u     = nullptr;
    for (int i = 0; i < n_in; i++) {
        if (in_sizes[i] == B_)                 d_index = (const int*)d_in[i];
        else if (in_sizes[i] == B_ * V_ * D_)  d_feats = (const float*)d_in[i];
        else                                   d_u     = (const float*)d_in[i];
    }
    float* out = (float*)d_out;

    cudaFuncSetAttribute(gemm_stats_kernel,
                         cudaFuncAttributeMaxDynamicSharedMemorySize, SMEM_BYTES);

    prep_kernel<<<NTOT * D_ / 4 / 256, 256>>>(d_feats);
    gemm_stats_kernel<<<NTILES, 256, SMEM_BYTES>>>();
    combine_loss_kernel<<<B_ / 256, 256>>>(d_index, d_u, out);
}

// round 10
// speedup vs baseline: 6.9738x; 1.0090x over previous
#include <cuda_runtime.h>
#include <cuda_fp16.h>
#include <stdint.h>

// ---------------- problem constants ----------------
#define B_    2048
#define V_    2
#define D_    256
#define NTOT  4096
#define NB_   32              // 128-wide blocks per dimension
#define NTILES 528            // NB*(NB+1)/2 upper-triangular tiles
#define GAMMA_F   0.9f
#define TEMP_F    0.07f
#define BASET_F   0.07f

// ---------------- device scratch ----------------
__device__ __half g_Fh[NTOT * D_];
__device__ float g_Mp[NB_ * NTOT];
__device__ float g_Ap[NB_ * NTOT];
__device__ float g_Wp[NB_ * NTOT];
__device__ float g_SP[NTOT];
__device__ float g_Lp[8];
__device__ unsigned int g_ctr;     // GEMM done counter
__device__ unsigned int g_fin;     // combine finish ticket

// ---------------- helpers ----------------
__device__ __forceinline__ uint32_t smem_u32(const void* p) {
    uint32_t a;
    asm("{ .reg .u64 t; cvta.to.shared.u64 t, %1; cvt.u32.u64 %0, t; }" : "=r"(a) : "l"(p));
    return a;
}
__device__ __forceinline__ uint32_t sw128(uint32_t off) {
    return off ^ ((off >> 3) & 0x70);
}
__device__ __forceinline__ void ldsm_x4(uint32_t* r, uint32_t addr) {
    asm volatile("ldmatrix.sync.aligned.m8n8.x4.shared.b16 {%0,%1,%2,%3}, [%4];"
                 : "=r"(r[0]), "=r"(r[1]), "=r"(r[2]), "=r"(r[3]) : "r"(addr));
}
__device__ __forceinline__ void mma_f16(float* c, const uint32_t* a, uint32_t b0, uint32_t b1) {
    asm volatile("mma.sync.aligned.m16n8k16.row.col.f32.f16.f16.f32 "
                 "{%0,%1,%2,%3}, {%4,%5,%6,%7}, {%8,%9}, {%0,%1,%2,%3};"
                 : "+f"(c[0]), "+f"(c[1]), "+f"(c[2]), "+f"(c[3])
                 : "r"(a[0]), "r"(a[1]), "r"(a[2]), "r"(a[3]), "r"(b0), "r"(b1));
}
__device__ __forceinline__ void cp16(uint32_t saddr, const void* gptr) {
    asm volatile("cp.async.cg.shared.global [%0], [%1], 16;"
                 :: "r"(saddr), "l"(__cvta_generic_to_global(gptr)));
}
#define CP_COMMIT() asm volatile("cp.async.commit_group;" ::: "memory")
#define CP_WAIT(n)  asm volatile("cp.async.wait_group %0;" :: "n"(n) : "memory")
__device__ __forceinline__ unsigned int ld_cg_u32(const unsigned int* p) {
    unsigned int v;
    asm volatile("ld.global.cg.u32 %0, [%1];" : "=r"(v) : "l"(p));
    return v;
}

// ---------------- kernel 1: rearrange -> fp16 (4x ILP) + counter reset ----------------
__global__ void prep_kernel(const float* __restrict__ feats) {
    if (blockIdx.x == 0 && threadIdx.x == 0) { g_ctr = 0; g_fin = 0; }
    int base = blockIdx.x * 1024 + threadIdx.x;   // 256 blocks x 4 quads/thread
    float4 f[4];
#pragma unroll
    for (int it = 0; it < 4; it++) {
        int e = (base + it * 256) * 4;
        int n = e >> 8;
        int d = e & 255;
        int v = n >> 11;
        int b = n & 2047;
        f[it] = *(const float4*)&feats[((b << 1) | v) * D_ + d];
    }
#pragma unroll
    for (int it = 0; it < 4; it++) {
        int e = (base + it * 256) * 4;
        uint2 hp;
        hp.x = ((uint32_t)__half_as_ushort(__float2half(f[it].y)) << 16) | __half_as_ushort(__float2half(f[it].x));
        hp.y = ((uint32_t)__half_as_ushort(__float2half(f[it].w)) << 16) | __half_as_ushort(__float2half(f[it].z));
        *(uint2*)&g_Fh[e] = hp;
    }
}

// ---------------- kernel 2: fused symmetric GEMM + stats + combine + loss ----------------
#define OFF_A 0
#define OFF_B 16384
#define STAGE_BYTES 32768
#define SMEM_BYTES  (2 * STAGE_BYTES)

__global__ void __launch_bounds__(256, 2) gemm_fused_kernel(const int* __restrict__ index,
                                                            const float* __restrict__ u,
                                                            float* __restrict__ out) {
    extern __shared__ char smem[];
    const uint32_t sb = smem_u32(smem);
    const int tid  = threadIdx.x;
    const int lane = tid & 31;
    const int wid  = tid >> 5;
    const int wm   = wid & 1;       // M half (64 rows)
    const int wn   = wid >> 1;      // N quarter (32 cols)

    // decode upper-triangular tile (bi, bj), bi <= bj
    int bi = 0, rem = blockIdx.x;
    while (rem >= (NB_ - bi)) { rem -= (NB_ - bi); bi++; }
    const int bj = bi + rem;
    const int row0 = bi * 128;
    const int col0 = bj * 128;

    // staging coords
    int sr[4], sc[4];
    uint32_t ssw[4];
#pragma unroll
    for (int it = 0; it < 4; it++) {
        int q = tid + it * 256;
        sr[it] = q >> 3;
        sc[it] = q & 7;
        ssw[it] = sw128((uint32_t)(sr[it] * 128 + sc[it] * 16));
    }

    // prefetch chunk 0 into stage 0
#pragma unroll
    for (int it = 0; it < 4; it++) {
        cp16(sb + OFF_A + ssw[it], &g_Fh[(row0 + sr[it]) * D_ + sc[it] * 8]);
        cp16(sb + OFF_B + ssw[it], &g_Fh[(col0 + sr[it]) * D_ + sc[it] * 8]);
    }
    CP_COMMIT();

    float acc[4][4][4];
#pragma unroll
    for (int mi = 0; mi < 4; mi++)
#pragma unroll
        for (int nj = 0; nj < 4; nj++)
#pragma unroll
            for (int c = 0; c < 4; c++) acc[mi][nj][c] = 0.0f;

    const int arow  = wm * 64 + (lane & 7) + ((lane >> 3) & 1) * 8;
    const int akc0  = (lane >> 4) * 8;
    const int brow  = wn * 32 + (lane & 7) + (lane >> 4) * 8;
    const int bkc0  = ((lane >> 3) & 1) * 8;

    for (int kc = 0; kc < 4; kc++) {
        if (kc < 3) {
            uint32_t nb = sb + ((kc + 1) & 1) * STAGE_BYTES;
#pragma unroll
            for (int it = 0; it < 4; it++) {
                cp16(nb + OFF_A + ssw[it], &g_Fh[(row0 + sr[it]) * D_ + (kc + 1) * 64 + sc[it] * 8]);
                cp16(nb + OFF_B + ssw[it], &g_Fh[(col0 + sr[it]) * D_ + (kc + 1) * 64 + sc[it] * 8]);
            }
            CP_COMMIT();
            CP_WAIT(1);
        } else {
            CP_WAIT(0);
        }
        __syncthreads();

        const uint32_t cb = sb + (kc & 1) * STAGE_BYTES;
#pragma unroll
        for (int ks = 0; ks < 4; ks++) {
            const int akc = ks * 16 + akc0;
            const int bkc = ks * 16 + bkc0;
            uint32_t a[4][4], b[2][4];
#pragma unroll
            for (int mi = 0; mi < 4; mi++)
                ldsm_x4(a[mi], cb + OFF_A + sw128((uint32_t)((arow + mi * 16) * 128 + akc * 2)));
#pragma unroll
            for (int b2 = 0; b2 < 2; b2++)
                ldsm_x4(b[b2], cb + OFF_B + sw128((uint32_t)((brow + b2 * 16) * 128 + bkc * 2)));
#pragma unroll
            for (int mi = 0; mi < 4; mi++)
#pragma unroll
                for (int nj = 0; nj < 4; nj++) {
                    uint32_t b0 = (nj & 1) ? b[nj >> 1][2] : b[nj >> 1][0];
                    uint32_t b1 = (nj & 1) ? b[nj >> 1][3] : b[nj >> 1][1];
                    mma_f16(acc[mi][nj], a[mi], b0, b1);
                }
        }
        __syncthreads();
    }

    // ---------------- epilogue: row/col stats ----------------
    float* redm = (float*)smem;          // [128][4] row partials
    float* reda = redm + 512;
    float* redw = reda + 512;
    float* colm = redw + 512;            // [128][2] col partials
    float* cola = colm + 256;
    float* colw = cola + 256;
    const float invT = 1.0f / TEMP_F;

#pragma unroll
    for (int mi = 0; mi < 4; mi++) {
#pragma unroll
        for (int h = 0; h < 2; h++) {
            int lr = wm * 64 + mi * 16 + h * 8 + (lane >> 2);
            int gi = row0 + lr;
            int posj = (gi + B_) & (NTOT - 1);
            float s[8];
#pragma unroll
            for (int nj = 0; nj < 4; nj++) {
                s[nj * 2]     = acc[mi][nj][h * 2]     * invT;
                s[nj * 2 + 1] = acc[mi][nj][h * 2 + 1] * invT;
            }
            float m = s[0];
#pragma unroll
            for (int i2 = 1; i2 < 8; i2++) m = fmaxf(m, s[i2]);
            m = fmaxf(m, __shfl_xor_sync(0xffffffffu, m, 1));
            m = fmaxf(m, __shfl_xor_sync(0xffffffffu, m, 2));
            float A = 0.0f, W = 0.0f;
#pragma unroll
            for (int nj = 0; nj < 4; nj++) {
#pragma unroll
                for (int c = 0; c < 2; c++) {
                    int gj = col0 + wn * 32 + nj * 8 + (lane & 3) * 2 + c;
                    float v = s[nj * 2 + c];
                    if (gj == posj) {
                        g_SP[gi] = v;
                    } else {
                        float e = __expf(v - m);
                        A += e;
                        W += e * (v - m);
                    }
                }
            }
            A += __shfl_xor_sync(0xffffffffu, A, 1);
            A += __shfl_xor_sync(0xffffffffu, A, 2);
            W += __shfl_xor_sync(0xffffffffu, W, 1);
            W += __shfl_xor_sync(0xffffffffu, W, 2);
            if ((lane & 3) == 0) {
                redm[lr * 4 + wn] = m;
                reda[lr * 4 + wn] = A;
                redw[lr * 4 + wn] = W;
            }
        }
    }

    if (bi != bj) {
#pragma unroll
        for (int nj = 0; nj < 4; nj++) {
#pragma unroll
            for (int cbx = 0; cbx < 2; cbx++) {
                int cid = wn * 32 + nj * 8 + (lane & 3) * 2 + cbx;
                int gj = col0 + cid;
                int posi = (gj + B_) & (NTOT - 1);
                float sv[8];
#pragma unroll
                for (int mi = 0; mi < 4; mi++) {
                    sv[mi * 2]     = acc[mi][nj][cbx]     * invT;
                    sv[mi * 2 + 1] = acc[mi][nj][2 + cbx] * invT;
                }
                float m = sv[0];
#pragma unroll
                for (int i2 = 1; i2 < 8; i2++) m = fmaxf(m, sv[i2]);
                m = fmaxf(m, __shfl_xor_sync(0xffffffffu, m, 4));
                m = fmaxf(m, __shfl_xor_sync(0xffffffffu, m, 8));
                m = fmaxf(m, __shfl_xor_sync(0xffffffffu, m, 16));
                float A = 0.0f, W = 0.0f;
#pragma unroll
                for (int mi = 0; mi < 4; mi++) {
#pragma unroll
                    for (int h = 0; h < 2; h++) {
                        int gi = row0 + wm * 64 + mi * 16 + h * 8 + (lane >> 2);
                        float v = sv[mi * 2 + h];
                        if (gi == posi) {
                            g_SP[gj] = v;          // S symmetric
                        } else {
                            float e = __expf(v - m);
                            A += e;
                            W += e * (v - m);
                        }
                    }
                }
                A += __shfl_xor_sync(0xffffffffu, A, 4);
                A += __shfl_xor_sync(0xffffffffu, A, 8);
                A += __shfl_xor_sync(0xffffffffu, A, 16);
                W += __shfl_xor_sync(0xffffffffu, W, 4);
                W += __shfl_xor_sync(0xffffffffu, W, 8);
                W += __shfl_xor_sync(0xffffffffu, W, 16);
                if ((lane >> 2) == 0) {
                    colm[cid * 2 + wm] = m;
                    cola[cid * 2 + wm] = A;
                    colw[cid * 2 + wm] = W;
                }
            }
        }
    }

    __syncthreads();
    if (tid < 128) {
        float mm = redm[tid * 4], aa = reda[tid * 4], ww = redw[tid * 4];
#pragma unroll
        for (int t = 1; t < 4; t++) {
            float m2 = redm[tid * 4 + t];
            float a2 = reda[tid * 4 + t];
            float w2 = redw[tid * 4 + t];
            float mN = fmaxf(mm, m2);
            float c1 = __expf(mm - mN);
            float c2 = __expf(m2 - mN);
            ww = c1 * (ww + (mm - mN) * aa) + c2 * (w2 + (m2 - mN) * a2);
            aa = c1 * aa + c2 * a2;
            mm = mN;
        }
        g_Mp[bj * NTOT + row0 + tid] = mm;
        g_Ap[bj * NTOT + row0 + tid] = aa;
        g_Wp[bj * NTOT + row0 + tid] = ww;
    } else if (bi != bj && tid < 256) {
        int cid = tid - 128;
        float m1 = colm[cid * 2],     a1 = cola[cid * 2],     w1 = colw[cid * 2];
        float m2 = colm[cid * 2 + 1], a2 = cola[cid * 2 + 1], w2 = colw[cid * 2 + 1];
        float mN = fmaxf(m1, m2);
        float c1 = __expf(m1 - mN), c2 = __expf(m2 - mN);
        float ww = c1 * (w1 + (m1 - mN) * a1) + c2 * (w2 + (m2 - mN) * a2);
        float aa = c1 * a1 + c2 * a2;
        g_Mp[bi * NTOT + col0 + cid] = mN;
        g_Ap[bi * NTOT + col0 + cid] = aa;
        g_Wp[bi * NTOT + col0 + cid] = ww;
    }

    // ---------------- done-ticket + fused combine (CTAs 0..7) ----------------
    __threadfence();          // each thread: make its global writes visible
    __syncthreads();
    if (tid == 0) atomicAdd(&g_ctr, 1u);

    if (blockIdx.x < 8) {
        if (tid == 0) {
            while (ld_cg_u32(&g_ctr) < (unsigned)NTILES) { __nanosleep(100); }
        }
        __syncthreads();
        __threadfence();      // acquire: see all partials

        __shared__ float red[8];
        int b = blockIdx.x * 256 + tid;            // [0, 2048)
        float m1 = -1e30f, a1 = 0.0f, w1 = 0.0f;   // row b
        float m2 = -1e30f, a2 = 0.0f, w2 = 0.0f;   // row b+2048
#pragma unroll
        for (int s = 0; s < NB_; s++) {
            {
                float mx = g_Mp[s * NTOT + b];
                float ax = g_Ap[s * NTOT + b];
                float wx = g_Wp[s * NTOT + b];
                float mN = fmaxf(m1, mx);
                float c1 = __expf(m1 - mN);
                float c2 = __expf(mx - mN);
                w1 = c1 * (w1 + (m1 - mN) * a1) + c2 * (wx + (mx - mN) * ax);
                a1 = c1 * a1 + c2 * ax;
                m1 = mN;
            }
            {
                float mx = g_Mp[s * NTOT + B_ + b];
                float ax = g_Ap[s * NTOT + B_ + b];
                float wx = g_Wp[s * NTOT + B_ + b];
                float mN = fmaxf(m2, mx);
                float c1 = __expf(m2 - mN);
                float c2 = __expf(mx - mN);
                w2 = c1 * (w2 + (m2 - mN) * a2) + c2 * (wx + (mx - mN) * ax);
                a2 = c1 * a2 + c2 * ax;
                m2 = mN;
            }
        }
        float u_new = (1.0f - GAMMA_F) * u[index[b]] + GAMMA_F * a1;
        const float k = -(TEMP_F / BASET_F) * (1.0f / (float)NTOT);
        float val = k * (((g_SP[b] - m1) - w1 / u_new) +
                         ((g_SP[B_ + b] - m2) - w2 / u_new));
#pragma unroll
        for (int o = 16; o; o >>= 1) val += __shfl_down_sync(0xffffffffu, val, o);
        if ((tid & 31) == 0) red[tid >> 5] = val;
        __syncthreads();
        if (tid < 8) {
            float v = red[tid];
#pragma unroll
            for (int o = 4; o; o >>= 1) v += __shfl_down_sync(0xffu, v, o);
            if (tid == 0) {
                g_Lp[blockIdx.x] = v;
                __threadfence();
                unsigned int t = atomicAdd(&g_fin, 1u);
                if (t == 7u) {                     // last combiner: fixed-order final sum
                    float s = 0.0f;
#pragma unroll
                    for (int i = 0; i < 8; i++) s += g_Lp[i];
                    out[0] = s;
                }
            }
        }
    }
}

// ---------------- launch ----------------
extern "C" void kernel_launch(void* const* d_in, const int* in_sizes, int n_in,
                              void* d_out, int out_size) {
    const int*   d_index = nullptr;
    const float* d_feats = nullptr;
    const float* d_u     = nullptr;
    for (int i = 0; i < n_in; i++) {
        if (in_sizes[i] == B_)                 d_index = (const int*)d_in[i];
        else if (in_sizes[i] == B_ * V_ * D_)  d_feats = (const float*)d_in[i];
        else                                   d_u     = (const float*)d_in[i];
    }
    float* out = (float*)d_out;

    cudaFuncSetAttribute(gemm_fused_kernel,
                         cudaFuncAttributeMaxDynamicSharedMemorySize, SMEM_BYTES);

    prep_kernel<<<NTOT * D_ / 16 / 256, 256>>>(d_feats);
    gemm_fused_kernel<<<NTILES, 256, SMEM_BYTES>>>(d_index, d_u, out);
}